// round 12
// baseline (speedup 1.0000x reference)
#include <cuda_runtime.h>
#include <cuda_bf16.h>
#include <cuda_fp16.h>
#include <math.h>
#include <stdint.h>

// ---------------- model dims ----------------
#define DD   768
#define HH   12
#define HDIM 64
#define DFF  3072
#define VV   32000
#define SS   2048
#define EPS  1e-5f

typedef __nv_bfloat16 bf16;

// ---------------- scratch (no allocs allowed) ----------------
__device__ float g_x   [SS * DD];
__device__ float g_qkv [SS * 3 * DD];
__device__ float g_proj[SS * DD];
__device__ float g_ln1 [SS * DD];
__device__ float g_f2  [SS * DD];

// bf16 path (attention out -> out-proj, bf16x3)
__device__ bf16 g_oh [SS * DD],  g_ol [SS * DD];
__device__ bf16 g_woh[DD * DD],  g_wol[DD * DD];

// fp16 activations (hi/lo) + weights (single)
__device__ __half g_xh16 [SS * DD],  g_xl16 [SS * DD];
__device__ __half g_l1h16[SS * DD],  g_l1l16[SS * DD];
__device__ __half g_f1h16[SS * DFF], g_f1l16[SS * DFF];
__device__ __half g_x16  [SS * DD];
__device__ __half g_wi16 [3 * DD * DD];
__device__ __half g_w116 [DFF * DD];
__device__ __half g_w216 [DD * DFF];
__device__ __half g_lm16 [VV * DD];

// ---------------- helpers ----------------
__device__ __forceinline__ uint32_t smem_u32(const void* p) {
    uint32_t a;
    asm("{ .reg .u64 t; cvta.to.shared.u64 t, %1; cvt.u32.u64 %0, t; }" : "=r"(a) : "l"(p));
    return a;
}
__device__ __forceinline__ void cp16(uint32_t sa, const void* g) {
    asm volatile("cp.async.cg.shared.global [%0], [%1], 16;" :: "r"(sa), "l"(g));
}
__device__ __forceinline__ void cp_commit() { asm volatile("cp.async.commit_group;" ::: "memory"); }
__device__ __forceinline__ void cp_wait0()  { asm volatile("cp.async.wait_group 0;" ::: "memory"); }
__device__ __forceinline__ void cp_wait1()  { asm volatile("cp.async.wait_group 1;" ::: "memory"); }
__device__ __forceinline__ void cp_wait2()  { asm volatile("cp.async.wait_group 2;" ::: "memory"); }

__device__ __forceinline__ void ldm_x4(uint32_t& r0, uint32_t& r1, uint32_t& r2, uint32_t& r3,
                                       uint32_t a) {
    asm volatile("ldmatrix.sync.aligned.m8n8.x4.shared.b16 {%0,%1,%2,%3}, [%4];"
                 : "=r"(r0), "=r"(r1), "=r"(r2), "=r"(r3) : "r"(a));
}
__device__ __forceinline__ void mma16816(float* d, const uint32_t* a, const uint32_t* b) {
    asm volatile(
        "mma.sync.aligned.m16n8k16.row.col.f32.bf16.bf16.f32 "
        "{%0,%1,%2,%3}, {%4,%5,%6,%7}, {%8,%9}, {%0,%1,%2,%3};"
        : "+f"(d[0]), "+f"(d[1]), "+f"(d[2]), "+f"(d[3])
        : "r"(a[0]), "r"(a[1]), "r"(a[2]), "r"(a[3]), "r"(b[0]), "r"(b[1]));
}
__device__ __forceinline__ void mma16816h(float* d, const uint32_t* a, const uint32_t* b) {
    asm volatile(
        "mma.sync.aligned.m16n8k16.row.col.f32.f16.f16.f32 "
        "{%0,%1,%2,%3}, {%4,%5,%6,%7}, {%8,%9}, {%0,%1,%2,%3};"
        : "+f"(d[0]), "+f"(d[1]), "+f"(d[2]), "+f"(d[3])
        : "r"(a[0]), "r"(a[1]), "r"(a[2]), "r"(a[3]), "r"(b[0]), "r"(b[1]));
}

__device__ __forceinline__ void split2(float v, bf16& h, bf16& l) {
    h = __float2bfloat16(v);
    l = __float2bfloat16(v - __bfloat162float(h));
}
__device__ __forceinline__ void split2h(float v, __half& h, __half& l) {
    h = __float2half_rn(v);
    l = __float2half_rn(v - __half2float(h));
}

// ---------------- conversion kernels ----------------
__global__ void split_kernel(const float* __restrict__ src,
                             bf16* __restrict__ hi, bf16* __restrict__ lo, int n4)
{
    int i = blockIdx.x * 256 + threadIdx.x;
    if (i >= n4) return;
    float4 v = reinterpret_cast<const float4*>(src)[i];
    bf16 h0, l0, h1, l1, h2, l2, h3, l3;
    split2(v.x, h0, l0); split2(v.y, h1, l1); split2(v.z, h2, l2); split2(v.w, h3, l3);
    __nv_bfloat162* H = reinterpret_cast<__nv_bfloat162*>(hi) + 2 * i;
    __nv_bfloat162* L = reinterpret_cast<__nv_bfloat162*>(lo) + 2 * i;
    H[0] = __nv_bfloat162(h0, h1); H[1] = __nv_bfloat162(h2, h3);
    L[0] = __nv_bfloat162(l0, l1); L[1] = __nv_bfloat162(l2, l3);
}

__global__ void cvt16_kernel(const float* __restrict__ src, __half* __restrict__ dst, int n4)
{
    int i = blockIdx.x * 256 + threadIdx.x;
    if (i >= n4) return;
    float4 v = reinterpret_cast<const float4*>(src)[i];
    __half2* D = reinterpret_cast<__half2*>(dst) + 2 * i;
    D[0] = __half2(__float2half_rn(v.x), __float2half_rn(v.y));
    D[1] = __half2(__float2half_rn(v.z), __float2half_rn(v.w));
}

__global__ void embed_kernel(const int* __restrict__ ids,
                             const float* __restrict__ ew,
                             const float* __restrict__ pe,
                             float* __restrict__ x,
                             __half* __restrict__ xh, __half* __restrict__ xl)
{
    int i = blockIdx.x * 256 + threadIdx.x;
    if (i >= SS * DD) return;
    int s = i / DD, d = i - s * DD;
    float v = ew[ids[s] * DD + d] * 27.712812921102035f + pe[i];
    x[i] = v;
    __half h, l; split2h(v, h, l);
    xh[i] = h; xl[i] = l;
}

// ---------------- fp16 2-pass GEMM: C = (Ah+Al) @ B^T (+bias)(+GELU) ----------------
// 128x128 tile, BK=32, 8 warps, 4 stages x 24KB, lookahead 2, ONE sync per chunk.
#define HSTG 24576
#define H2_SMEM (4 * HSTG + 128)

__global__ __launch_bounds__(256, 2)
void gemm_h2(const __half* __restrict__ Ah, const __half* __restrict__ Al,
             const __half* __restrict__ B, const float* __restrict__ bias,
             float* __restrict__ Cf, __half* __restrict__ C16h, __half* __restrict__ C16l,
             int M, int N, int K, int act)
{
    extern __shared__ char dsm[];
    uint32_t sbase = (smem_u32(dsm) + 127u) & ~127u;

    const int tid = threadIdx.x, lane = tid & 31, wid = tid >> 5;
    const int m0 = blockIdx.x * 128, n0 = blockIdx.y * 128;
    const int warp_m = (wid >> 1) * 32, warp_n = (wid & 1) * 64;

    // 6 x 16B loads/thread/chunk (3 tiles x 128 rows x 4 chunks = 1536)
    const __half* gbase[6];
    uint32_t      sofs[6];
#pragma unroll
    for (int t = 0; t < 6; t++) {
        int id = tid + (t << 8);
        int tl = id >> 9;                 // 0:Ah 1:Al 2:B
        int idx = id & 511;
        int r = idx >> 2, j = idx & 3;
        const __half* g;
        if      (tl == 0) g = Ah + (size_t)(m0 + r) * K;
        else if (tl == 1) g = Al + (size_t)(m0 + r) * K;
        else              g = B  + (size_t)(n0 + r) * K;
        gbase[t] = g + j * 8;
        sofs[t]  = (uint32_t)(tl * 8192 + r * 64 + ((j ^ ((r >> 1) & 3)) << 4));
    }

    const int lr = lane & 7, lb1 = (lane >> 3) & 1, lb2 = lane >> 4;
    uint32_t aoff[2][2], boff[4][2];
#pragma unroll
    for (int mi = 0; mi < 2; mi++)
#pragma unroll
        for (int ks = 0; ks < 2; ks++) {
            int r = warp_m + mi * 16 + lr + lb1 * 8;
            int j = ks * 2 + lb2;
            aoff[mi][ks] = (uint32_t)(r * 64 + ((j ^ ((r >> 1) & 3)) << 4));
        }
#pragma unroll
    for (int nb = 0; nb < 4; nb++)
#pragma unroll
        for (int ks = 0; ks < 2; ks++) {
            int r = warp_n + nb * 16 + lr + lb2 * 8;
            int j = ks * 2 + lb1;
            boff[nb][ks] = (uint32_t)(r * 64 + 16384 + ((j ^ ((r >> 1) & 3)) << 4));
        }

    float acc[2][8][4];
#pragma unroll
    for (int mi = 0; mi < 2; mi++)
#pragma unroll
        for (int ni = 0; ni < 8; ni++)
#pragma unroll
            for (int r = 0; r < 4; r++) acc[mi][ni][r] = 0.f;

    const int NC = K >> 5;

    {
        uint32_t st = sbase;
#pragma unroll
        for (int t = 0; t < 6; t++) cp16(st + sofs[t], gbase[t]);
        cp_commit();
        st = sbase + HSTG;
#pragma unroll
        for (int t = 0; t < 6; t++) cp16(st + sofs[t], gbase[t] + 32);
        cp_commit();
    }

    for (int c = 0; c < NC; c++) {
        if (c + 2 < NC) {
            uint32_t st = sbase + ((c + 2) & 3) * HSTG;
            const int koff = (c + 2) << 5;
#pragma unroll
            for (int t = 0; t < 6; t++) cp16(st + sofs[t], gbase[t] + koff);
            cp_commit();
            cp_wait2();
        } else if (c + 1 < NC) {
            cp_wait1();
        } else {
            cp_wait0();
        }
        __syncthreads();

        uint32_t st = sbase + (c & 3) * HSTG;
#pragma unroll
        for (int ks = 0; ks < 2; ks++) {
            uint32_t afh[2][4], afl[2][4];
            ldm_x4(afh[0][0], afh[0][1], afh[0][2], afh[0][3], st + aoff[0][ks]);
            ldm_x4(afh[1][0], afh[1][1], afh[1][2], afh[1][3], st + aoff[1][ks]);
            ldm_x4(afl[0][0], afl[0][1], afl[0][2], afl[0][3], st + 8192 + aoff[0][ks]);
            ldm_x4(afl[1][0], afl[1][1], afl[1][2], afl[1][3], st + 8192 + aoff[1][ks]);
#pragma unroll
            for (int nh = 0; nh < 2; nh++) {
                uint32_t bfr[4][2];
                ldm_x4(bfr[0][0], bfr[0][1], bfr[1][0], bfr[1][1], st + boff[2 * nh][ks]);
                ldm_x4(bfr[2][0], bfr[2][1], bfr[3][0], bfr[3][1], st + boff[2 * nh + 1][ks]);
#pragma unroll
                for (int mi = 0; mi < 2; mi++)
#pragma unroll
                    for (int nj = 0; nj < 4; nj++) {
                        mma16816h(acc[mi][4 * nh + nj], afh[mi], bfr[nj]);
                        mma16816h(acc[mi][4 * nh + nj], afl[mi], bfr[nj]);
                    }
            }
        }
        // no trailing sync: 4 stages + lookahead 2 keep writes off live stages
    }

#pragma unroll
    for (int mi = 0; mi < 2; mi++) {
        int rbase = m0 + warp_m + mi * 16 + (lane >> 2);
#pragma unroll
        for (int ni = 0; ni < 8; ni++) {
            int col = n0 + warp_n + ni * 8 + (lane & 3) * 2;
            float bv0 = 0.f, bv1 = 0.f;
            if (bias) { bv0 = bias[col]; bv1 = bias[col + 1]; }
#pragma unroll
            for (int hf = 0; hf < 2; hf++) {
                int row = rbase + hf * 8;
                float v0 = acc[mi][ni][hf * 2 + 0] + bv0;
                float v1 = acc[mi][ni][hf * 2 + 1] + bv1;
                if (act) {
                    v0 = 0.5f * v0 * (1.f + erff(v0 * 0.70710678118654752f));
                    v1 = 0.5f * v1 * (1.f + erff(v1 * 0.70710678118654752f));
                }
                size_t idx = (size_t)row * N + col;
                if (Cf) { Cf[idx] = v0; Cf[idx + 1] = v1; }
                if (C16h) {
                    __half h0, l0, h1, l1;
                    split2h(v0, h0, l0); split2h(v1, h1, l1);
                    *reinterpret_cast<__half2*>(C16h + idx) = __half2(h0, h1);
                    *reinterpret_cast<__half2*>(C16l + idx) = __half2(l0, l1);
                }
            }
        }
    }
}

// ---------------- bf16x3 HMMA GEMM (out-proj only) ----------------
#define STG 32768
#define GEMM_SMEM (3 * STG + 128)

__global__ __launch_bounds__(256, 2)
void gemm_mma(const bf16* __restrict__ Ah, const bf16* __restrict__ Al,
              const bf16* __restrict__ Bh, const bf16* __restrict__ Bl,
              const float* __restrict__ bias, float* __restrict__ Cf,
              int M, int N, int K)
{
    extern __shared__ char dsm[];
    uint32_t sbase = (smem_u32(dsm) + 127u) & ~127u;

    const int tid = threadIdx.x, lane = tid & 31, wid = tid >> 5;
    const int m0 = blockIdx.x * 128, n0 = blockIdx.y * 128;
    const int warp_m = (wid >> 1) * 32, warp_n = (wid & 1) * 64;

    const bf16* gbase[8];
    uint32_t    sofs[8];
#pragma unroll
    for (int t = 0; t < 8; t++) {
        int id = tid + (t << 8);
        int tl = id >> 9;
        int idx = id & 511;
        int r = idx >> 2, j = idx & 3;
        const bf16* g;
        if      (tl == 0) g = Ah + (size_t)(m0 + r) * K;
        else if (tl == 1) g = Al + (size_t)(m0 + r) * K;
        else if (tl == 2) g = Bh + (size_t)(n0 + r) * K;
        else              g = Bl + (size_t)(n0 + r) * K;
        gbase[t] = g + j * 8;
        sofs[t]  = (uint32_t)(tl * 8192 + r * 64 + ((j ^ ((r >> 1) & 3)) << 4));
    }

    const int lr = lane & 7, lb1 = (lane >> 3) & 1, lb2 = lane >> 4;
    uint32_t aoff[2][2], boff[4][2];
#pragma unroll
    for (int mi = 0; mi < 2; mi++)
#pragma unroll
        for (int ks = 0; ks < 2; ks++) {
            int r = warp_m + mi * 16 + lr + lb1 * 8;
            int j = ks * 2 + lb2;
            aoff[mi][ks] = (uint32_t)(r * 64 + ((j ^ ((r >> 1) & 3)) << 4));
        }
#pragma unroll
    for (int nb = 0; nb < 4; nb++)
#pragma unroll
        for (int ks = 0; ks < 2; ks++) {
            int r = warp_n + nb * 16 + lr + lb2 * 8;
            int j = ks * 2 + lb1;
            boff[nb][ks] = (uint32_t)(r * 64 + ((j ^ ((r >> 1) & 3)) << 4));
        }

    float acc[2][8][4];
#pragma unroll
    for (int mi = 0; mi < 2; mi++)
#pragma unroll
        for (int ni = 0; ni < 8; ni++)
#pragma unroll
            for (int r = 0; r < 4; r++) acc[mi][ni][r] = 0.f;

    const int NC = K >> 5;

    {
        uint32_t st = sbase;
#pragma unroll
        for (int t = 0; t < 8; t++) cp16(st + sofs[t], gbase[t]);
        cp_commit();
        if (NC > 1) {
            st = sbase + STG;
#pragma unroll
            for (int t = 0; t < 8; t++) cp16(st + sofs[t], gbase[t] + 32);
            cp_commit();
        }
    }

    int stage = 0;
    for (int c = 0; c < NC; c++) {
        if (c + 2 < NC) {
            int ls = stage + 2; if (ls >= 3) ls -= 3;
            uint32_t st = sbase + ls * STG;
            const int koff = (c + 2) << 5;
#pragma unroll
            for (int t = 0; t < 8; t++) cp16(st + sofs[t], gbase[t] + koff);
            cp_commit();
            cp_wait2();
        } else if (c + 1 < NC) {
            cp_wait1();
        } else {
            cp_wait0();
        }
        __syncthreads();

        uint32_t st = sbase + stage * STG;
        const uint32_t ah_b = st, al_b = st + 8192, bh_b = st + 16384, bl_b = st + 24576;
#pragma unroll
        for (int ks = 0; ks < 2; ks++) {
            uint32_t afh[2][4], afl[2][4];
            ldm_x4(afh[0][0], afh[0][1], afh[0][2], afh[0][3], ah_b + aoff[0][ks]);
            ldm_x4(afh[1][0], afh[1][1], afh[1][2], afh[1][3], ah_b + aoff[1][ks]);
            ldm_x4(afl[0][0], afl[0][1], afl[0][2], afl[0][3], al_b + aoff[0][ks]);
            ldm_x4(afl[1][0], afl[1][1], afl[1][2], afl[1][3], al_b + aoff[1][ks]);
#pragma unroll
            for (int nh = 0; nh < 2; nh++) {
                uint32_t bh[4][2], bl[4][2];
                ldm_x4(bh[0][0], bh[0][1], bh[1][0], bh[1][1], bh_b + boff[2 * nh][ks]);
                ldm_x4(bh[2][0], bh[2][1], bh[3][0], bh[3][1], bh_b + boff[2 * nh + 1][ks]);
                ldm_x4(bl[0][0], bl[0][1], bl[1][0], bl[1][1], bl_b + boff[2 * nh][ks]);
                ldm_x4(bl[2][0], bl[2][1], bl[3][0], bl[3][1], bl_b + boff[2 * nh + 1][ks]);
#pragma unroll
                for (int mi = 0; mi < 2; mi++)
#pragma unroll
                    for (int nj = 0; nj < 4; nj++) {
                        mma16816(acc[mi][4 * nh + nj], afh[mi], bh[nj]);
                        mma16816(acc[mi][4 * nh + nj], afh[mi], bl[nj]);
                        mma16816(acc[mi][4 * nh + nj], afl[mi], bh[nj]);
                    }
            }
        }
        __syncthreads();
        stage++; if (stage >= 3) stage = 0;
    }

#pragma unroll
    for (int mi = 0; mi < 2; mi++) {
        int rbase = m0 + warp_m + mi * 16 + (lane >> 2);
#pragma unroll
        for (int ni = 0; ni < 8; ni++) {
            int col = n0 + warp_n + ni * 8 + (lane & 3) * 2;
            float bv0 = bias ? bias[col] : 0.f;
            float bv1 = bias ? bias[col + 1] : 0.f;
#pragma unroll
            for (int hf = 0; hf < 2; hf++) {
                int row = rbase + hf * 8;
                size_t idx = (size_t)row * N + col;
                Cf[idx]     = acc[mi][ni][hf * 2 + 0] + bv0;
                Cf[idx + 1] = acc[mi][ni][hf * 2 + 1] + bv1;
            }
        }
    }
}

// ---------------- LM head GEMM: C = A @ B^T, single-pass fp16 ----------------
#define LSTG 16384
#define LM_SMEM (4 * LSTG + 128)

__global__ __launch_bounds__(256, 2)
void lm_gemm(const __half* __restrict__ A, const __half* __restrict__ B,
             float* __restrict__ Cf, int M, int N, int K)
{
    extern __shared__ char dsm[];
    uint32_t sbase = (smem_u32(dsm) + 127u) & ~127u;

    const int tid = threadIdx.x, lane = tid & 31, wid = tid >> 5;
    const int m0 = blockIdx.x * 128, n0 = blockIdx.y * 128;
    const int warp_m = (wid >> 1) * 32, warp_n = (wid & 1) * 64;

    const __half* gbase[4];
    uint32_t      sofs[4];
#pragma unroll
    for (int t = 0; t < 4; t++) {
        int id = tid + (t << 8);
        int tl = id >> 9;
        int idx = id & 511;
        int r = idx >> 2, j = idx & 3;
        const __half* g = tl ? (B + (size_t)(n0 + r) * K) : (A + (size_t)(m0 + r) * K);
        gbase[t] = g + j * 8;
        sofs[t]  = (uint32_t)(tl * 8192 + r * 64 + ((j ^ ((r >> 1) & 3)) << 4));
    }

    const int lr = lane & 7, lb1 = (lane >> 3) & 1, lb2 = lane >> 4;
    uint32_t aoff[2][2], boff[4][2];
#pragma unroll
    for (int mi = 0; mi < 2; mi++)
#pragma unroll
        for (int ks = 0; ks < 2; ks++) {
            int r = warp_m + mi * 16 + lr + lb1 * 8;
            int j = ks * 2 + lb2;
            aoff[mi][ks] = (uint32_t)(r * 64 + ((j ^ ((r >> 1) & 3)) << 4));
        }
#pragma unroll
    for (int nb = 0; nb < 4; nb++)
#pragma unroll
        for (int ks = 0; ks < 2; ks++) {
            int r = warp_n + nb * 16 + lr + lb2 * 8;
            int j = ks * 2 + lb1;
            boff[nb][ks] = (uint32_t)(r * 64 + 8192 + ((j ^ ((r >> 1) & 3)) << 4));
        }

    float acc[2][8][4];
#pragma unroll
    for (int mi = 0; mi < 2; mi++)
#pragma unroll
        for (int ni = 0; ni < 8; ni++)
#pragma unroll
            for (int r = 0; r < 4; r++) acc[mi][ni][r] = 0.f;

    const int NC = K >> 5;

    {
        uint32_t st = sbase;
#pragma unroll
        for (int t = 0; t < 4; t++) cp16(st + sofs[t], gbase[t]);
        cp_commit();
        st = sbase + LSTG;
#pragma unroll
        for (int t = 0; t < 4; t++) cp16(st + sofs[t], gbase[t] + 32);
        cp_commit();
    }

    for (int c = 0; c < NC; c++) {
        if (c + 2 < NC) {
            uint32_t st = sbase + ((c + 2) & 3) * LSTG;
            const int koff = (c + 2) << 5;
#pragma unroll
            for (int t = 0; t < 4; t++) cp16(st + sofs[t], gbase[t] + koff);
            cp_commit();
            cp_wait2();
        } else if (c + 1 < NC) {
            cp_wait1();
        } else {
            cp_wait0();
        }
        __syncthreads();

        uint32_t st = sbase + (c & 3) * LSTG;
#pragma unroll
        for (int ks = 0; ks < 2; ks++) {
            uint32_t af[2][4];
            ldm_x4(af[0][0], af[0][1], af[0][2], af[0][3], st + aoff[0][ks]);
            ldm_x4(af[1][0], af[1][1], af[1][2], af[1][3], st + aoff[1][ks]);
#pragma unroll
            for (int nh = 0; nh < 2; nh++) {
                uint32_t bh[4][2];
                ldm_x4(bh[0][0], bh[0][1], bh[1][0], bh[1][1], st + boff[2 * nh][ks]);
                ldm_x4(bh[2][0], bh[2][1], bh[3][0], bh[3][1], st + boff[2 * nh + 1][ks]);
#pragma unroll
                for (int mi = 0; mi < 2; mi++)
#pragma unroll
                    for (int nj = 0; nj < 4; nj++)
                        mma16816h(acc[mi][4 * nh + nj], af[mi], bh[nj]);
            }
        }
    }

#pragma unroll
    for (int mi = 0; mi < 2; mi++) {
        int rbase = m0 + warp_m + mi * 16 + (lane >> 2);
#pragma unroll
        for (int ni = 0; ni < 8; ni++) {
            int col = n0 + warp_n + ni * 8 + (lane & 3) * 2;
#pragma unroll
            for (int hf = 0; hf < 2; hf++) {
                int row = rbase + hf * 8;
                size_t idx = (size_t)row * N + col;
                Cf[idx]     = acc[mi][ni][hf * 2 + 0];
                Cf[idx + 1] = acc[mi][ni][hf * 2 + 1];
            }
        }
    }
}

// ---------------- causal flash attention (SIMT, fp32, 32-key subtiles) ----------------
__global__ __launch_bounds__(128)
void attn_kernel(const float* __restrict__ qkv,
                 bf16* __restrict__ oh, bf16* __restrict__ ol)
{
    __shared__ float Ks[64][64];
    __shared__ float Vs[64][64];

    const int h = blockIdx.y;
    const int tid = threadIdx.x;
    const int q_idx = blockIdx.x * 128 + tid;
    const int q_blk_end = blockIdx.x * 128 + 127;

    float q[HDIM];
    const float* qrow = qkv + (size_t)q_idx * (3 * DD) + h * HDIM;
#pragma unroll
    for (int d = 0; d < HDIM; d++) q[d] = qrow[d];

    float m = -1e30f, l = 0.f;
    float acc[HDIM];
#pragma unroll
    for (int d = 0; d < HDIM; d++) acc[d] = 0.f;

    for (int kt = 0; kt * 64 <= q_blk_end; kt++) {
#pragma unroll
        for (int r = 0; r < 8; r++) {
            int id  = tid + r * 128;
            int row = id >> 4;
            int c4  = (id & 15) << 2;
            const float* base = qkv + (size_t)(kt * 64 + row) * (3 * DD) + h * HDIM + c4;
            *reinterpret_cast<float4*>(&Ks[row][c4]) = *reinterpret_cast<const float4*>(base + DD);
            *reinterpret_cast<float4*>(&Vs[row][c4]) = *reinterpret_cast<const float4*>(base + 2 * DD);
        }
        __syncthreads();

#pragma unroll
        for (int sub = 0; sub < 2; sub++) {
            const int base = kt * 64 + sub * 32;
            if (base > q_idx) break;
            int jmax = q_idx - base;
            if (jmax > 31) jmax = 31;

            float s[32];
            float smax = -1e30f;
            for (int j = 0; j <= jmax; j++) {
                float acc_s = 0.f;
#pragma unroll
                for (int d = 0; d < HDIM; d++) acc_s += q[d] * Ks[sub * 32 + j][d];
                acc_s *= 0.125f;
                s[j] = acc_s;
                smax = fmaxf(smax, acc_s);
            }
            float mnew = fmaxf(m, smax);
            float corr = __expf(m - mnew);
            l *= corr;
#pragma unroll
            for (int d = 0; d < HDIM; d++) acc[d] *= corr;
            for (int j = 0; j <= jmax; j++) {
                float p = __expf(s[j] - mnew);
                l += p;
#pragma unroll
                for (int d = 0; d < HDIM; d++) acc[d] += p * Vs[sub * 32 + j][d];
            }
            m = mnew;
        }
        __syncthreads();
    }

    float inv = 1.f / l;
    size_t ob = (size_t)q_idx * DD + h * HDIM;
#pragma unroll
    for (int d = 0; d < HDIM; d++) {
        float v = acc[d] * inv;
        bf16 hh, ll; split2(v, hh, ll);
        oh[ob + d] = hh; ol[ob + d] = ll;
    }
}

// ---------------- add + LayerNorm (fp32 out and/or fp16 hi/lo out) ----------------
__device__ __forceinline__ float warp_sum(float v)
{
#pragma unroll
    for (int o = 16; o > 0; o >>= 1) v += __shfl_xor_sync(0xffffffffu, v, o);
    return v;
}

__global__ __launch_bounds__(256)
void add_ln_kernel(const float* __restrict__ x, const float* __restrict__ y,
                   const float* __restrict__ g, const float* __restrict__ b,
                   float* __restrict__ out,
                   __half* __restrict__ outh, __half* __restrict__ outl)
{
    __shared__ float buf[DD];
    __shared__ float red[8];
    const int row = blockIdx.x;
    const int tid = threadIdx.x;
    const int wid = tid >> 5, lane = tid & 31;

    float local = 0.f;
    for (int d = tid; d < DD; d += 256) {
        float v = x[(size_t)row * DD + d] + y[(size_t)row * DD + d];
        buf[d] = v;
        local += v;
    }
    local = warp_sum(local);
    if (lane == 0) red[wid] = local;
    __syncthreads();
    float tot = (lane < 8) ? red[lane] : 0.f;
    tot = warp_sum(tot);
    float mu = __shfl_sync(0xffffffffu, tot, 0) * (1.f / DD);

    float lv = 0.f;
    for (int d = tid; d < DD; d += 256) {
        float t = buf[d] - mu;
        lv += t * t;
    }
    lv = warp_sum(lv);
    __syncthreads();
    if (lane == 0) red[wid] = lv;
    __syncthreads();
    float tv = (lane < 8) ? red[lane] : 0.f;
    tv = warp_sum(tv);
    float rstd = rsqrtf(__shfl_sync(0xffffffffu, tv, 0) * (1.f / DD) + EPS);

    for (int d = tid; d < DD; d += 256) {
        float v = (buf[d] - mu) * rstd * g[d] + b[d];
        size_t idx = (size_t)row * DD + d;
        if (out) out[idx] = v;
        if (outh) {
            if (outl) {
                __half h, l; split2h(v, h, l);
                outh[idx] = h; outl[idx] = l;
            } else {
                outh[idx] = __float2half_rn(v);
            }
        }
    }
}

// ---------------- launch ----------------
extern "C" void kernel_launch(void* const* d_in, const int* in_sizes, int n_in,
                              void* d_out, int out_size)
{
    const int*   ids = (const int*)  d_in[0];
    const float* ew  = (const float*)d_in[1];
    const float* pe  = (const float*)d_in[2];
    const float* inw = (const float*)d_in[3];
    const float* inb = (const float*)d_in[4];
    const float* ow  = (const float*)d_in[5];
    const float* ob  = (const float*)d_in[6];
    const float* ng  = (const float*)d_in[7];
    const float* nb  = (const float*)d_in[8];
    const float* w1  = (const float*)d_in[9];
    const float* b1  = (const float*)d_in[10];
    const float* w2  = (const float*)d_in[11];
    const float* b2  = (const float*)d_in[12];
    const float* lmw = (const float*)d_in[13];
    float* out = (float*)d_out;

    float *x, *qkv, *proj, *ln1, *f2;
    bf16 *oh, *ol, *woh, *wol;
    __half *xh16, *xl16, *l1h16, *l1l16, *f1h16, *f1l16, *x16;
    __half *wi16, *w116, *w216, *lm16;
    cudaGetSymbolAddress((void**)&x,    g_x);
    cudaGetSymbolAddress((void**)&qkv,  g_qkv);
    cudaGetSymbolAddress((void**)&proj, g_proj);
    cudaGetSymbolAddress((void**)&ln1,  g_ln1);
    cudaGetSymbolAddress((void**)&f2,   g_f2);
    cudaGetSymbolAddress((void**)&oh,   g_oh);  cudaGetSymbolAddress((void**)&ol,  g_ol);
    cudaGetSymbolAddress((void**)&woh,  g_woh); cudaGetSymbolAddress((void**)&wol, g_wol);
    cudaGetSymbolAddress((void**)&xh16, g_xh16);  cudaGetSymbolAddress((void**)&xl16, g_xl16);
    cudaGetSymbolAddress((void**)&l1h16,g_l1h16); cudaGetSymbolAddress((void**)&l1l16,g_l1l16);
    cudaGetSymbolAddress((void**)&f1h16,g_f1h16); cudaGetSymbolAddress((void**)&f1l16,g_f1l16);
    cudaGetSymbolAddress((void**)&x16,  g_x16);
    cudaGetSymbolAddress((void**)&wi16, g_wi16);
    cudaGetSymbolAddress((void**)&w116, g_w116);
    cudaGetSymbolAddress((void**)&w216, g_w216);
    cudaGetSymbolAddress((void**)&lm16, g_lm16);

    cudaFuncSetAttribute(gemm_mma, cudaFuncAttributeMaxDynamicSharedMemorySize, GEMM_SMEM);
    cudaFuncSetAttribute(gemm_h2,  cudaFuncAttributeMaxDynamicSharedMemorySize, H2_SMEM);
    cudaFuncSetAttribute(lm_gemm,  cudaFuncAttributeMaxDynamicSharedMemorySize, LM_SMEM);

    // 0-3: weight conversions (fp16)
    cvt16_kernel<<<(3 * DD * DD / 4 + 255) / 256, 256>>>(inw, wi16, 3 * DD * DD / 4);
    cvt16_kernel<<<(DFF * DD / 4 + 255) / 256, 256>>>(w1, w116, DFF * DD / 4);
    cvt16_kernel<<<(DD * DFF / 4 + 255) / 256, 256>>>(w2, w216, DD * DFF / 4);
    cvt16_kernel<<<(VV * DD / 4 + 255) / 256, 256>>>(lmw, lm16, VV * DD / 4);

    // 4: embed (+fp16 hi/lo split)
    embed_kernel<<<(SS * DD + 255) / 256, 256>>>(ids, ew, pe, x, xh16, xl16);

    // 5: qkv = x @ in_proj_w^T + b   [2048, 2304]  (fp16 2-pass) — profiled slot
    gemm_h2<<<dim3(SS / 128, (3 * DD) / 128), 256, H2_SMEM>>>(
        xh16, xl16, wi16, inb, qkv, nullptr, nullptr, SS, 3 * DD, DD, 0);

    // 6: out-proj weight split (bf16 hi/lo)
    split_kernel<<<(DD * DD / 4 + 255) / 256, 256>>>(ow, woh, wol, DD * DD / 4);

    // 7: attention -> o (bf16 hi/lo)
    attn_kernel<<<dim3(SS / 128, HH), 128>>>(qkv, oh, ol);

    // 8: out proj (bf16x3)           [2048, 768]
    gemm_mma<<<dim3(SS / 128, DD / 128), 256, GEMM_SMEM>>>(
        oh, ol, woh, wol, ob, proj, SS, DD, DD);

    // 9: ln1 = LN(x + proj) -> fp32 + fp16 hi/lo
    add_ln_kernel<<<SS, 256>>>(x, proj, ng, nb, ln1, l1h16, l1l16);

    // 10: f1 = gelu(ln1 @ w1^T + b1) [2048, 3072] -> fp16 hi/lo (fp16 2-pass)
    gemm_h2<<<dim3(SS / 128, DFF / 128), 256, H2_SMEM>>>(
        l1h16, l1l16, w116, b1, nullptr, f1h16, f1l16, SS, DFF, DD, 1);

    // 11: f2 = f1 @ w2^T + b2        [2048, 768] (fp16 2-pass)
    gemm_h2<<<dim3(SS / 128, DD / 128), 256, H2_SMEM>>>(
        f1h16, f1l16, w216, b2, f2, nullptr, nullptr, SS, DD, DFF, 0);

    // 12: x2 = LN(ln1 + f2) -> fp16 single
    add_ln_kernel<<<SS, 256>>>(ln1, f2, ng, nb, nullptr, x16, nullptr);

    // 13: logits = x2 @ lm16^T       [2048, 32000] single-pass fp16
    lm_gemm<<<dim3(SS / 128, VV / 128), 256, LM_SMEM>>>(x16, lm16, out, SS, VV, DD);
}

// round 14
// speedup vs baseline: 1.5489x; 1.5489x over previous
#include <cuda_runtime.h>
#include <cuda_bf16.h>
#include <cuda_fp16.h>
#include <math.h>
#include <stdint.h>

// ---------------- model dims ----------------
#define DD   768
#define HH   12
#define HDIM 64
#define DFF  3072
#define VV   32000
#define SS   2048
#define EPS  1e-5f

typedef __nv_bfloat16 bf16;

// ---------------- scratch (no allocs allowed) ----------------
__device__ float g_x   [SS * DD];
__device__ float g_qkv [SS * 3 * DD];
__device__ float g_proj[SS * DD];
__device__ float g_ln1 [SS * DD];
__device__ float g_f2  [SS * DD];

// bf16 path (attention out -> out-proj, bf16x3)
__device__ bf16 g_oh [SS * DD],  g_ol [SS * DD];
__device__ bf16 g_woh[DD * DD],  g_wol[DD * DD];

// fp16 activations (hi/lo) + weights (single)
__device__ __half g_xh16 [SS * DD],  g_xl16 [SS * DD];
__device__ __half g_l1h16[SS * DD],  g_l1l16[SS * DD];
__device__ __half g_f1h16[SS * DFF], g_f1l16[SS * DFF];
__device__ __half g_x16  [SS * DD];
__device__ __half g_wi16 [3 * DD * DD];
__device__ __half g_w116 [DFF * DD];
__device__ __half g_w216 [DD * DFF];
__device__ __half g_lm16 [VV * DD];

// ---------------- helpers ----------------
__device__ __forceinline__ uint32_t smem_u32(const void* p) {
    uint32_t a;
    asm("{ .reg .u64 t; cvta.to.shared.u64 t, %1; cvt.u32.u64 %0, t; }" : "=r"(a) : "l"(p));
    return a;
}
__device__ __forceinline__ void cp16(uint32_t sa, const void* g) {
    asm volatile("cp.async.cg.shared.global [%0], [%1], 16;" :: "r"(sa), "l"(g));
}
__device__ __forceinline__ void cp_commit() { asm volatile("cp.async.commit_group;" ::: "memory"); }
__device__ __forceinline__ void cp_wait0()  { asm volatile("cp.async.wait_group 0;" ::: "memory"); }
__device__ __forceinline__ void cp_wait1()  { asm volatile("cp.async.wait_group 1;" ::: "memory"); }
__device__ __forceinline__ void cp_wait2()  { asm volatile("cp.async.wait_group 2;" ::: "memory"); }

__device__ __forceinline__ void ldm_x4(uint32_t& r0, uint32_t& r1, uint32_t& r2, uint32_t& r3,
                                       uint32_t a) {
    asm volatile("ldmatrix.sync.aligned.m8n8.x4.shared.b16 {%0,%1,%2,%3}, [%4];"
                 : "=r"(r0), "=r"(r1), "=r"(r2), "=r"(r3) : "r"(a));
}
__device__ __forceinline__ void mma16816(float* d, const uint32_t* a, const uint32_t* b) {
    asm volatile(
        "mma.sync.aligned.m16n8k16.row.col.f32.bf16.bf16.f32 "
        "{%0,%1,%2,%3}, {%4,%5,%6,%7}, {%8,%9}, {%0,%1,%2,%3};"
        : "+f"(d[0]), "+f"(d[1]), "+f"(d[2]), "+f"(d[3])
        : "r"(a[0]), "r"(a[1]), "r"(a[2]), "r"(a[3]), "r"(b[0]), "r"(b[1]));
}
__device__ __forceinline__ void mma16816h(float* d, const uint32_t* a, const uint32_t* b) {
    asm volatile(
        "mma.sync.aligned.m16n8k16.row.col.f32.f16.f16.f32 "
        "{%0,%1,%2,%3}, {%4,%5,%6,%7}, {%8,%9}, {%0,%1,%2,%3};"
        : "+f"(d[0]), "+f"(d[1]), "+f"(d[2]), "+f"(d[3])
        : "r"(a[0]), "r"(a[1]), "r"(a[2]), "r"(a[3]), "r"(b[0]), "r"(b[1]));
}

__device__ __forceinline__ void split2(float v, bf16& h, bf16& l) {
    h = __float2bfloat16(v);
    l = __float2bfloat16(v - __bfloat162float(h));
}
__device__ __forceinline__ void split2h(float v, __half& h, __half& l) {
    h = __float2half_rn(v);
    l = __float2half_rn(v - __half2float(h));
}

// ---------------- conversion kernels ----------------
__global__ void split_kernel(const float* __restrict__ src,
                             bf16* __restrict__ hi, bf16* __restrict__ lo, int n4)
{
    int i = blockIdx.x * 256 + threadIdx.x;
    if (i >= n4) return;
    float4 v = reinterpret_cast<const float4*>(src)[i];
    bf16 h0, l0, h1, l1, h2, l2, h3, l3;
    split2(v.x, h0, l0); split2(v.y, h1, l1); split2(v.z, h2, l2); split2(v.w, h3, l3);
    __nv_bfloat162* H = reinterpret_cast<__nv_bfloat162*>(hi) + 2 * i;
    __nv_bfloat162* L = reinterpret_cast<__nv_bfloat162*>(lo) + 2 * i;
    H[0] = __nv_bfloat162(h0, h1); H[1] = __nv_bfloat162(h2, h3);
    L[0] = __nv_bfloat162(l0, l1); L[1] = __nv_bfloat162(l2, l3);
}

__global__ void cvt16_kernel(const float* __restrict__ src, __half* __restrict__ dst, int n4)
{
    int i = blockIdx.x * 256 + threadIdx.x;
    if (i >= n4) return;
    float4 v = reinterpret_cast<const float4*>(src)[i];
    __half2* D = reinterpret_cast<__half2*>(dst) + 2 * i;
    D[0] = __half2(__float2half_rn(v.x), __float2half_rn(v.y));
    D[1] = __half2(__float2half_rn(v.z), __float2half_rn(v.w));
}

__global__ void embed_kernel(const int* __restrict__ ids,
                             const float* __restrict__ ew,
                             const float* __restrict__ pe,
                             float* __restrict__ x,
                             __half* __restrict__ xh, __half* __restrict__ xl)
{
    int i = blockIdx.x * 256 + threadIdx.x;
    if (i >= SS * DD) return;
    int s = i / DD, d = i - s * DD;
    float v = ew[ids[s] * DD + d] * 27.712812921102035f + pe[i];
    x[i] = v;
    __half h, l; split2h(v, h, l);
    xh[i] = h; xl[i] = l;
}

// ---------------- fp16 2-pass GEMM (hidden layers) — gemm_mma skeleton ----------------
// C = (Ah+Al) @ B^T (+bias)(+GELU). 128x128 tile, BK=32, 8 warps,
// 3 stages x 24KB, lookahead 2, trailing __syncthreads (PROVEN skeleton).
#define HSTG 24576
#define H2_SMEM (3 * HSTG + 128)

__global__ __launch_bounds__(256, 2)
void gemm_h2(const __half* __restrict__ Ah, const __half* __restrict__ Al,
             const __half* __restrict__ B, const float* __restrict__ bias,
             float* __restrict__ Cf, __half* __restrict__ C16h, __half* __restrict__ C16l,
             int M, int N, int K, int act)
{
    extern __shared__ char dsm[];
    uint32_t sbase = (smem_u32(dsm) + 127u) & ~127u;

    const int tid = threadIdx.x, lane = tid & 31, wid = tid >> 5;
    const int m0 = blockIdx.x * 128, n0 = blockIdx.y * 128;
    const int warp_m = (wid >> 1) * 32, warp_n = (wid & 1) * 64;

    // 6 x 16B loads/thread/chunk (3 tiles x 128 rows x 4 chunks = 1536)
    const __half* gbase[6];
    uint32_t      sofs[6];
#pragma unroll
    for (int t = 0; t < 6; t++) {
        int id = tid + (t << 8);
        int tl = id >> 9;                 // 0:Ah 1:Al 2:B
        int idx = id & 511;
        int r = idx >> 2, j = idx & 3;
        const __half* g;
        if      (tl == 0) g = Ah + (size_t)(m0 + r) * K;
        else if (tl == 1) g = Al + (size_t)(m0 + r) * K;
        else              g = B  + (size_t)(n0 + r) * K;
        gbase[t] = g + j * 8;
        sofs[t]  = (uint32_t)(tl * 8192 + r * 64 + ((j ^ ((r >> 1) & 3)) << 4));
    }

    const int lr = lane & 7, lb1 = (lane >> 3) & 1, lb2 = lane >> 4;
    uint32_t aoff[2][2], boff[4][2];
#pragma unroll
    for (int mi = 0; mi < 2; mi++)
#pragma unroll
        for (int ks = 0; ks < 2; ks++) {
            int r = warp_m + mi * 16 + lr + lb1 * 8;
            int j = ks * 2 + lb2;
            aoff[mi][ks] = (uint32_t)(r * 64 + ((j ^ ((r >> 1) & 3)) << 4));
        }
#pragma unroll
    for (int nb = 0; nb < 4; nb++)
#pragma unroll
        for (int ks = 0; ks < 2; ks++) {
            int r = warp_n + nb * 16 + lr + lb2 * 8;
            int j = ks * 2 + lb1;
            boff[nb][ks] = (uint32_t)(r * 64 + 16384 + ((j ^ ((r >> 1) & 3)) << 4));
        }

    float acc[2][8][4];
#pragma unroll
    for (int mi = 0; mi < 2; mi++)
#pragma unroll
        for (int ni = 0; ni < 8; ni++)
#pragma unroll
            for (int r = 0; r < 4; r++) acc[mi][ni][r] = 0.f;

    const int NC = K >> 5;

    // prologue: chunks 0,1 -> stages 0,1
    {
        uint32_t st = sbase;
#pragma unroll
        for (int t = 0; t < 6; t++) cp16(st + sofs[t], gbase[t]);
        cp_commit();
        if (NC > 1) {
            st = sbase + HSTG;
#pragma unroll
            for (int t = 0; t < 6; t++) cp16(st + sofs[t], gbase[t] + 32);
            cp_commit();
        }
    }

    int stage = 0;
    for (int c = 0; c < NC; c++) {
        if (c + 2 < NC) {
            int ls = stage + 2; if (ls >= 3) ls -= 3;
            uint32_t st = sbase + ls * HSTG;
            const int koff = (c + 2) << 5;
#pragma unroll
            for (int t = 0; t < 6; t++) cp16(st + sofs[t], gbase[t] + koff);
            cp_commit();
            cp_wait2();
        } else if (c + 1 < NC) {
            cp_wait1();
        } else {
            cp_wait0();
        }
        __syncthreads();

        uint32_t st = sbase + stage * HSTG;
#pragma unroll
        for (int ks = 0; ks < 2; ks++) {
            uint32_t afh[2][4], afl[2][4];
            ldm_x4(afh[0][0], afh[0][1], afh[0][2], afh[0][3], st + aoff[0][ks]);
            ldm_x4(afh[1][0], afh[1][1], afh[1][2], afh[1][3], st + aoff[1][ks]);
            ldm_x4(afl[0][0], afl[0][1], afl[0][2], afl[0][3], st + 8192 + aoff[0][ks]);
            ldm_x4(afl[1][0], afl[1][1], afl[1][2], afl[1][3], st + 8192 + aoff[1][ks]);
#pragma unroll
            for (int nh = 0; nh < 2; nh++) {
                uint32_t bfr[4][2];
                ldm_x4(bfr[0][0], bfr[0][1], bfr[1][0], bfr[1][1], st + boff[2 * nh][ks]);
                ldm_x4(bfr[2][0], bfr[2][1], bfr[3][0], bfr[3][1], st + boff[2 * nh + 1][ks]);
#pragma unroll
                for (int mi = 0; mi < 2; mi++)
#pragma unroll
                    for (int nj = 0; nj < 4; nj++) {
                        mma16816h(acc[mi][4 * nh + nj], afh[mi], bfr[nj]);
                        mma16816h(acc[mi][4 * nh + nj], afl[mi], bfr[nj]);
                    }
            }
        }
        __syncthreads();
        stage++; if (stage >= 3) stage = 0;
    }

#pragma unroll
    for (int mi = 0; mi < 2; mi++) {
        int rbase = m0 + warp_m + mi * 16 + (lane >> 2);
#pragma unroll
        for (int ni = 0; ni < 8; ni++) {
            int col = n0 + warp_n + ni * 8 + (lane & 3) * 2;
            float bv0 = 0.f, bv1 = 0.f;
            if (bias) { bv0 = bias[col]; bv1 = bias[col + 1]; }
#pragma unroll
            for (int hf = 0; hf < 2; hf++) {
                int row = rbase + hf * 8;
                float v0 = acc[mi][ni][hf * 2 + 0] + bv0;
                float v1 = acc[mi][ni][hf * 2 + 1] + bv1;
                if (act) {
                    v0 = 0.5f * v0 * (1.f + erff(v0 * 0.70710678118654752f));
                    v1 = 0.5f * v1 * (1.f + erff(v1 * 0.70710678118654752f));
                }
                size_t idx = (size_t)row * N + col;
                if (Cf) { Cf[idx] = v0; Cf[idx + 1] = v1; }
                if (C16h) {
                    __half h0, l0, h1, l1;
                    split2h(v0, h0, l0); split2h(v1, h1, l1);
                    *reinterpret_cast<__half2*>(C16h + idx) = __half2(h0, h1);
                    *reinterpret_cast<__half2*>(C16l + idx) = __half2(l0, l1);
                }
            }
        }
    }
}

// ---------------- bf16x3 HMMA GEMM (out-proj only) ----------------
#define STG 32768
#define GEMM_SMEM (3 * STG + 128)

__global__ __launch_bounds__(256, 2)
void gemm_mma(const bf16* __restrict__ Ah, const bf16* __restrict__ Al,
              const bf16* __restrict__ Bh, const bf16* __restrict__ Bl,
              const float* __restrict__ bias, float* __restrict__ Cf,
              int M, int N, int K)
{
    extern __shared__ char dsm[];
    uint32_t sbase = (smem_u32(dsm) + 127u) & ~127u;

    const int tid = threadIdx.x, lane = tid & 31, wid = tid >> 5;
    const int m0 = blockIdx.x * 128, n0 = blockIdx.y * 128;
    const int warp_m = (wid >> 1) * 32, warp_n = (wid & 1) * 64;

    const bf16* gbase[8];
    uint32_t    sofs[8];
#pragma unroll
    for (int t = 0; t < 8; t++) {
        int id = tid + (t << 8);
        int tl = id >> 9;
        int idx = id & 511;
        int r = idx >> 2, j = idx & 3;
        const bf16* g;
        if      (tl == 0) g = Ah + (size_t)(m0 + r) * K;
        else if (tl == 1) g = Al + (size_t)(m0 + r) * K;
        else if (tl == 2) g = Bh + (size_t)(n0 + r) * K;
        else              g = Bl + (size_t)(n0 + r) * K;
        gbase[t] = g + j * 8;
        sofs[t]  = (uint32_t)(tl * 8192 + r * 64 + ((j ^ ((r >> 1) & 3)) << 4));
    }

    const int lr = lane & 7, lb1 = (lane >> 3) & 1, lb2 = lane >> 4;
    uint32_t aoff[2][2], boff[4][2];
#pragma unroll
    for (int mi = 0; mi < 2; mi++)
#pragma unroll
        for (int ks = 0; ks < 2; ks++) {
            int r = warp_m + mi * 16 + lr + lb1 * 8;
            int j = ks * 2 + lb2;
            aoff[mi][ks] = (uint32_t)(r * 64 + ((j ^ ((r >> 1) & 3)) << 4));
        }
#pragma unroll
    for (int nb = 0; nb < 4; nb++)
#pragma unroll
        for (int ks = 0; ks < 2; ks++) {
            int r = warp_n + nb * 16 + lr + lb2 * 8;
            int j = ks * 2 + lb1;
            boff[nb][ks] = (uint32_t)(r * 64 + ((j ^ ((r >> 1) & 3)) << 4));
        }

    float acc[2][8][4];
#pragma unroll
    for (int mi = 0; mi < 2; mi++)
#pragma unroll
        for (int ni = 0; ni < 8; ni++)
#pragma unroll
            for (int r = 0; r < 4; r++) acc[mi][ni][r] = 0.f;

    const int NC = K >> 5;

    {
        uint32_t st = sbase;
#pragma unroll
        for (int t = 0; t < 8; t++) cp16(st + sofs[t], gbase[t]);
        cp_commit();
        if (NC > 1) {
            st = sbase + STG;
#pragma unroll
            for (int t = 0; t < 8; t++) cp16(st + sofs[t], gbase[t] + 32);
            cp_commit();
        }
    }

    int stage = 0;
    for (int c = 0; c < NC; c++) {
        if (c + 2 < NC) {
            int ls = stage + 2; if (ls >= 3) ls -= 3;
            uint32_t st = sbase + ls * STG;
            const int koff = (c + 2) << 5;
#pragma unroll
            for (int t = 0; t < 8; t++) cp16(st + sofs[t], gbase[t] + koff);
            cp_commit();
            cp_wait2();
        } else if (c + 1 < NC) {
            cp_wait1();
        } else {
            cp_wait0();
        }
        __syncthreads();

        uint32_t st = sbase + stage * STG;
        const uint32_t ah_b = st, al_b = st + 8192, bh_b = st + 16384, bl_b = st + 24576;
#pragma unroll
        for (int ks = 0; ks < 2; ks++) {
            uint32_t afh[2][4], afl[2][4];
            ldm_x4(afh[0][0], afh[0][1], afh[0][2], afh[0][3], ah_b + aoff[0][ks]);
            ldm_x4(afh[1][0], afh[1][1], afh[1][2], afh[1][3], ah_b + aoff[1][ks]);
            ldm_x4(afl[0][0], afl[0][1], afl[0][2], afl[0][3], al_b + aoff[0][ks]);
            ldm_x4(afl[1][0], afl[1][1], afl[1][2], afl[1][3], al_b + aoff[1][ks]);
#pragma unroll
            for (int nh = 0; nh < 2; nh++) {
                uint32_t bh[4][2], bl[4][2];
                ldm_x4(bh[0][0], bh[0][1], bh[1][0], bh[1][1], bh_b + boff[2 * nh][ks]);
                ldm_x4(bh[2][0], bh[2][1], bh[3][0], bh[3][1], bh_b + boff[2 * nh + 1][ks]);
                ldm_x4(bl[0][0], bl[0][1], bl[1][0], bl[1][1], bl_b + boff[2 * nh][ks]);
                ldm_x4(bl[2][0], bl[2][1], bl[3][0], bl[3][1], bl_b + boff[2 * nh + 1][ks]);
#pragma unroll
                for (int mi = 0; mi < 2; mi++)
#pragma unroll
                    for (int nj = 0; nj < 4; nj++) {
                        mma16816(acc[mi][4 * nh + nj], afh[mi], bh[nj]);
                        mma16816(acc[mi][4 * nh + nj], afh[mi], bl[nj]);
                        mma16816(acc[mi][4 * nh + nj], afl[mi], bh[nj]);
                    }
            }
        }
        __syncthreads();
        stage++; if (stage >= 3) stage = 0;
    }

#pragma unroll
    for (int mi = 0; mi < 2; mi++) {
        int rbase = m0 + warp_m + mi * 16 + (lane >> 2);
#pragma unroll
        for (int ni = 0; ni < 8; ni++) {
            int col = n0 + warp_n + ni * 8 + (lane & 3) * 2;
            float bv0 = bias ? bias[col] : 0.f;
            float bv1 = bias ? bias[col + 1] : 0.f;
#pragma unroll
            for (int hf = 0; hf < 2; hf++) {
                int row = rbase + hf * 8;
                size_t idx = (size_t)row * N + col;
                Cf[idx]     = acc[mi][ni][hf * 2 + 0] + bv0;
                Cf[idx + 1] = acc[mi][ni][hf * 2 + 1] + bv1;
            }
        }
    }
}

// ---------------- LM head GEMM: C = A @ B^T, single-pass fp16 (proven) ----------------
#define LSTG 16384
#define LM_SMEM (4 * LSTG + 128)

__global__ __launch_bounds__(256, 2)
void lm_gemm(const __half* __restrict__ A, const __half* __restrict__ B,
             float* __restrict__ Cf, int M, int N, int K)
{
    extern __shared__ char dsm[];
    uint32_t sbase = (smem_u32(dsm) + 127u) & ~127u;

    const int tid = threadIdx.x, lane = tid & 31, wid = tid >> 5;
    const int m0 = blockIdx.x * 128, n0 = blockIdx.y * 128;
    const int warp_m = (wid >> 1) * 32, warp_n = (wid & 1) * 64;

    const __half* gbase[4];
    uint32_t      sofs[4];
#pragma unroll
    for (int t = 0; t < 4; t++) {
        int id = tid + (t << 8);
        int tl = id >> 9;
        int idx = id & 511;
        int r = idx >> 2, j = idx & 3;
        const __half* g = tl ? (B + (size_t)(n0 + r) * K) : (A + (size_t)(m0 + r) * K);
        gbase[t] = g + j * 8;
        sofs[t]  = (uint32_t)(tl * 8192 + r * 64 + ((j ^ ((r >> 1) & 3)) << 4));
    }

    const int lr = lane & 7, lb1 = (lane >> 3) & 1, lb2 = lane >> 4;
    uint32_t aoff[2][2], boff[4][2];
#pragma unroll
    for (int mi = 0; mi < 2; mi++)
#pragma unroll
        for (int ks = 0; ks < 2; ks++) {
            int r = warp_m + mi * 16 + lr + lb1 * 8;
            int j = ks * 2 + lb2;
            aoff[mi][ks] = (uint32_t)(r * 64 + ((j ^ ((r >> 1) & 3)) << 4));
        }
#pragma unroll
    for (int nb = 0; nb < 4; nb++)
#pragma unroll
        for (int ks = 0; ks < 2; ks++) {
            int r = warp_n + nb * 16 + lr + lb2 * 8;
            int j = ks * 2 + lb1;
            boff[nb][ks] = (uint32_t)(r * 64 + 8192 + ((j ^ ((r >> 1) & 3)) << 4));
        }

    float acc[2][8][4];
#pragma unroll
    for (int mi = 0; mi < 2; mi++)
#pragma unroll
        for (int ni = 0; ni < 8; ni++)
#pragma unroll
            for (int r = 0; r < 4; r++) acc[mi][ni][r] = 0.f;

    const int NC = K >> 5;

    {
        uint32_t st = sbase;
#pragma unroll
        for (int t = 0; t < 4; t++) cp16(st + sofs[t], gbase[t]);
        cp_commit();
        st = sbase + LSTG;
#pragma unroll
        for (int t = 0; t < 4; t++) cp16(st + sofs[t], gbase[t] + 32);
        cp_commit();
    }

    for (int c = 0; c < NC; c++) {
        if (c + 2 < NC) {
            uint32_t st = sbase + ((c + 2) & 3) * LSTG;
            const int koff = (c + 2) << 5;
#pragma unroll
            for (int t = 0; t < 4; t++) cp16(st + sofs[t], gbase[t] + koff);
            cp_commit();
            cp_wait2();
        } else if (c + 1 < NC) {
            cp_wait1();
        } else {
            cp_wait0();
        }
        __syncthreads();

        uint32_t st = sbase + (c & 3) * LSTG;
#pragma unroll
        for (int ks = 0; ks < 2; ks++) {
            uint32_t af[2][4];
            ldm_x4(af[0][0], af[0][1], af[0][2], af[0][3], st + aoff[0][ks]);
            ldm_x4(af[1][0], af[1][1], af[1][2], af[1][3], st + aoff[1][ks]);
#pragma unroll
            for (int nh = 0; nh < 2; nh++) {
                uint32_t bh[4][2];
                ldm_x4(bh[0][0], bh[0][1], bh[1][0], bh[1][1], st + boff[2 * nh][ks]);
                ldm_x4(bh[2][0], bh[2][1], bh[3][0], bh[3][1], st + boff[2 * nh + 1][ks]);
#pragma unroll
                for (int mi = 0; mi < 2; mi++)
#pragma unroll
                    for (int nj = 0; nj < 4; nj++)
                        mma16816h(acc[mi][4 * nh + nj], af[mi], bh[nj]);
            }
        }
    }

#pragma unroll
    for (int mi = 0; mi < 2; mi++) {
        int rbase = m0 + warp_m + mi * 16 + (lane >> 2);
#pragma unroll
        for (int ni = 0; ni < 8; ni++) {
            int col = n0 + warp_n + ni * 8 + (lane & 3) * 2;
#pragma unroll
            for (int hf = 0; hf < 2; hf++) {
                int row = rbase + hf * 8;
                size_t idx = (size_t)row * N + col;
                Cf[idx]     = acc[mi][ni][hf * 2 + 0];
                Cf[idx + 1] = acc[mi][ni][hf * 2 + 1];
            }
        }
    }
}

// ---------------- causal flash attention (SIMT, fp32, 32-key subtiles) ----------------
__global__ __launch_bounds__(128)
void attn_kernel(const float* __restrict__ qkv,
                 bf16* __restrict__ oh, bf16* __restrict__ ol)
{
    __shared__ float Ks[64][64];
    __shared__ float Vs[64][64];

    const int h = blockIdx.y;
    const int tid = threadIdx.x;
    const int q_idx = blockIdx.x * 128 + tid;
    const int q_blk_end = blockIdx.x * 128 + 127;

    float q[HDIM];
    const float* qrow = qkv + (size_t)q_idx * (3 * DD) + h * HDIM;
#pragma unroll
    for (int d = 0; d < HDIM; d++) q[d] = qrow[d];

    float m = -1e30f, l = 0.f;
    float acc[HDIM];
#pragma unroll
    for (int d = 0; d < HDIM; d++) acc[d] = 0.f;

    for (int kt = 0; kt * 64 <= q_blk_end; kt++) {
#pragma unroll
        for (int r = 0; r < 8; r++) {
            int id  = tid + r * 128;
            int row = id >> 4;
            int c4  = (id & 15) << 2;
            const float* base = qkv + (size_t)(kt * 64 + row) * (3 * DD) + h * HDIM + c4;
            *reinterpret_cast<float4*>(&Ks[row][c4]) = *reinterpret_cast<const float4*>(base + DD);
            *reinterpret_cast<float4*>(&Vs[row][c4]) = *reinterpret_cast<const float4*>(base + 2 * DD);
        }
        __syncthreads();

#pragma unroll
        for (int sub = 0; sub < 2; sub++) {
            const int base = kt * 64 + sub * 32;
            if (base > q_idx) break;
            int jmax = q_idx - base;
            if (jmax > 31) jmax = 31;

            float s[32];
            float smax = -1e30f;
            for (int j = 0; j <= jmax; j++) {
                float acc_s = 0.f;
#pragma unroll
                for (int d = 0; d < HDIM; d++) acc_s += q[d] * Ks[sub * 32 + j][d];
                acc_s *= 0.125f;
                s[j] = acc_s;
                smax = fmaxf(smax, acc_s);
            }
            float mnew = fmaxf(m, smax);
            float corr = __expf(m - mnew);
            l *= corr;
#pragma unroll
            for (int d = 0; d < HDIM; d++) acc[d] *= corr;
            for (int j = 0; j <= jmax; j++) {
                float p = __expf(s[j] - mnew);
                l += p;
#pragma unroll
                for (int d = 0; d < HDIM; d++) acc[d] += p * Vs[sub * 32 + j][d];
            }
            m = mnew;
        }
        __syncthreads();
    }

    float inv = 1.f / l;
    size_t ob = (size_t)q_idx * DD + h * HDIM;
#pragma unroll
    for (int d = 0; d < HDIM; d++) {
        float v = acc[d] * inv;
        bf16 hh, ll; split2(v, hh, ll);
        oh[ob + d] = hh; ol[ob + d] = ll;
    }
}

// ---------------- add + LayerNorm (fp32 out and/or fp16 hi/lo out) ----------------
__device__ __forceinline__ float warp_sum(float v)
{
#pragma unroll
    for (int o = 16; o > 0; o >>= 1) v += __shfl_xor_sync(0xffffffffu, v, o);
    return v;
}

__global__ __launch_bounds__(256)
void add_ln_kernel(const float* __restrict__ x, const float* __restrict__ y,
                   const float* __restrict__ g, const float* __restrict__ b,
                   float* __restrict__ out,
                   __half* __restrict__ outh, __half* __restrict__ outl)
{
    __shared__ float buf[DD];
    __shared__ float red[8];
    const int row = blockIdx.x;
    const int tid = threadIdx.x;
    const int wid = tid >> 5, lane = tid & 31;

    float local = 0.f;
    for (int d = tid; d < DD; d += 256) {
        float v = x[(size_t)row * DD + d] + y[(size_t)row * DD + d];
        buf[d] = v;
        local += v;
    }
    local = warp_sum(local);
    if (lane == 0) red[wid] = local;
    __syncthreads();
    float tot = (lane < 8) ? red[lane] : 0.f;
    tot = warp_sum(tot);
    float mu = __shfl_sync(0xffffffffu, tot, 0) * (1.f / DD);

    float lv = 0.f;
    for (int d = tid; d < DD; d += 256) {
        float t = buf[d] - mu;
        lv += t * t;
    }
    lv = warp_sum(lv);
    __syncthreads();
    if (lane == 0) red[wid] = lv;
    __syncthreads();
    float tv = (lane < 8) ? red[lane] : 0.f;
    tv = warp_sum(tv);
    float rstd = rsqrtf(__shfl_sync(0xffffffffu, tv, 0) * (1.f / DD) + EPS);

    for (int d = tid; d < DD; d += 256) {
        float v = (buf[d] - mu) * rstd * g[d] + b[d];
        size_t idx = (size_t)row * DD + d;
        if (out) out[idx] = v;
        if (outh) {
            if (outl) {
                __half h, l; split2h(v, h, l);
                outh[idx] = h; outl[idx] = l;
            } else {
                outh[idx] = __float2half_rn(v);
            }
        }
    }
}

// ---------------- launch ----------------
extern "C" void kernel_launch(void* const* d_in, const int* in_sizes, int n_in,
                              void* d_out, int out_size)
{
    const int*   ids = (const int*)  d_in[0];
    const float* ew  = (const float*)d_in[1];
    const float* pe  = (const float*)d_in[2];
    const float* inw = (const float*)d_in[3];
    const float* inb = (const float*)d_in[4];
    const float* ow  = (const float*)d_in[5];
    const float* ob  = (const float*)d_in[6];
    const float* ng  = (const float*)d_in[7];
    const float* nb  = (const float*)d_in[8];
    const float* w1  = (const float*)d_in[9];
    const float* b1  = (const float*)d_in[10];
    const float* w2  = (const float*)d_in[11];
    const float* b2  = (const float*)d_in[12];
    const float* lmw = (const float*)d_in[13];
    float* out = (float*)d_out;

    float *x, *qkv, *proj, *ln1, *f2;
    bf16 *oh, *ol, *woh, *wol;
    __half *xh16, *xl16, *l1h16, *l1l16, *f1h16, *f1l16, *x16;
    __half *wi16, *w116, *w216, *lm16;
    cudaGetSymbolAddress((void**)&x,    g_x);
    cudaGetSymbolAddress((void**)&qkv,  g_qkv);
    cudaGetSymbolAddress((void**)&proj, g_proj);
    cudaGetSymbolAddress((void**)&ln1,  g_ln1);
    cudaGetSymbolAddress((void**)&f2,   g_f2);
    cudaGetSymbolAddress((void**)&oh,   g_oh);  cudaGetSymbolAddress((void**)&ol,  g_ol);
    cudaGetSymbolAddress((void**)&woh,  g_woh); cudaGetSymbolAddress((void**)&wol, g_wol);
    cudaGetSymbolAddress((void**)&xh16, g_xh16);  cudaGetSymbolAddress((void**)&xl16, g_xl16);
    cudaGetSymbolAddress((void**)&l1h16,g_l1h16); cudaGetSymbolAddress((void**)&l1l16,g_l1l16);
    cudaGetSymbolAddress((void**)&f1h16,g_f1h16); cudaGetSymbolAddress((void**)&f1l16,g_f1l16);
    cudaGetSymbolAddress((void**)&x16,  g_x16);
    cudaGetSymbolAddress((void**)&wi16, g_wi16);
    cudaGetSymbolAddress((void**)&w116, g_w116);
    cudaGetSymbolAddress((void**)&w216, g_w216);
    cudaGetSymbolAddress((void**)&lm16, g_lm16);

    cudaFuncSetAttribute(gemm_mma, cudaFuncAttributeMaxDynamicSharedMemorySize, GEMM_SMEM);
    cudaFuncSetAttribute(gemm_h2,  cudaFuncAttributeMaxDynamicSharedMemorySize, H2_SMEM);
    cudaFuncSetAttribute(lm_gemm,  cudaFuncAttributeMaxDynamicSharedMemorySize, LM_SMEM);

    // weight conversions
    cvt16_kernel<<<(3 * DD * DD / 4 + 255) / 256, 256>>>(inw, wi16, 3 * DD * DD / 4);
    cvt16_kernel<<<(DFF * DD / 4 + 255) / 256, 256>>>(w1, w116, DFF * DD / 4);
    cvt16_kernel<<<(DD * DFF / 4 + 255) / 256, 256>>>(w2, w216, DD * DFF / 4);
    cvt16_kernel<<<(VV * DD / 4 + 255) / 256, 256>>>(lmw, lm16, VV * DD / 4);

    // embed (+fp16 hi/lo split)
    embed_kernel<<<(SS * DD + 255) / 256, 256>>>(ids, ew, pe, x, xh16, xl16);

    // qkv = x @ in_proj_w^T + b   [2048, 2304]  (fp16 2-pass, proven skeleton)
    gemm_h2<<<dim3(SS / 128, (3 * DD) / 128), 256, H2_SMEM>>>(
        xh16, xl16, wi16, inb, qkv, nullptr, nullptr, SS, 3 * DD, DD, 0);

    // out-proj weight split (bf16 hi/lo)
    split_kernel<<<(DD * DD / 4 + 255) / 256, 256>>>(ow, woh, wol, DD * DD / 4);

    // attention -> o (bf16 hi/lo)
    attn_kernel<<<dim3(SS / 128, HH), 128>>>(qkv, oh, ol);

    // out proj (bf16x3)           [2048, 768]
    gemm_mma<<<dim3(SS / 128, DD / 128), 256, GEMM_SMEM>>>(
        oh, ol, woh, wol, ob, proj, SS, DD, DD);

    // ln1 = LN(x + proj) -> fp32 + fp16 hi/lo
    add_ln_kernel<<<SS, 256>>>(x, proj, ng, nb, ln1, l1h16, l1l16);

    // f1 = gelu(ln1 @ w1^T + b1) [2048, 3072] -> fp16 hi/lo (fp16 2-pass)
    gemm_h2<<<dim3(SS / 128, DFF / 128), 256, H2_SMEM>>>(
        l1h16, l1l16, w116, b1, nullptr, f1h16, f1l16, SS, DFF, DD, 1);

    // f2 = f1 @ w2^T + b2        [2048, 768] (fp16 2-pass)
    gemm_h2<<<dim3(SS / 128, DD / 128), 256, H2_SMEM>>>(
        f1h16, f1l16, w216, b2, f2, nullptr, nullptr, SS, DD, DFF, 0);

    // x2 = LN(ln1 + f2) -> fp16 single
    add_ln_kernel<<<SS, 256>>>(ln1, f2, ng, nb, nullptr, x16, nullptr);

    // logits = x2 @ lm16^T       [2048, 32000] single-pass fp16
    lm_gemm<<<dim3(SS / 128, VV / 128), 256, LM_SMEM>>>(x16, lm16, out, SS, VV, DD);
}

// round 15
// speedup vs baseline: 1.8812x; 1.2145x over previous
#include <cuda_runtime.h>
#include <cuda_bf16.h>
#include <cuda_fp16.h>
#include <math.h>
#include <stdint.h>

// ---------------- model dims ----------------
#define DD   768
#define HH   12
#define HDIM 64
#define DFF  3072
#define VV   32000
#define SS   2048
#define EPS  1e-5f
#define MAXSP 8

typedef __nv_bfloat16 bf16;

// ---------------- scratch (no allocs allowed) ----------------
__device__ float g_x   [SS * DD];
__device__ float g_qkv [SS * 3 * DD];
__device__ float g_proj[SS * DD];
__device__ float g_ln1 [SS * DD];
__device__ float g_f2  [SS * DD];

// split-KV attention partials (SoA, q-major for coalescing)
__device__ float g_mpart  [HH * MAXSP * SS];
__device__ float g_lpart  [HH * MAXSP * SS];
__device__ float g_accpart[HH * MAXSP * HDIM * SS];

// bf16 path (attention out -> out-proj, bf16x3)
__device__ bf16 g_oh [SS * DD],  g_ol [SS * DD];
__device__ bf16 g_woh[DD * DD],  g_wol[DD * DD];

// fp16 activations (hi/lo) + weights (single)
__device__ __half g_xh16 [SS * DD],  g_xl16 [SS * DD];
__device__ __half g_l1h16[SS * DD],  g_l1l16[SS * DD];
__device__ __half g_f1h16[SS * DFF], g_f1l16[SS * DFF];
__device__ __half g_x16  [SS * DD];
__device__ __half g_wi16 [3 * DD * DD];
__device__ __half g_w116 [DFF * DD];
__device__ __half g_w216 [DD * DFF];
__device__ __half g_lm16 [VV * DD];

// ---------------- helpers ----------------
__device__ __forceinline__ uint32_t smem_u32(const void* p) {
    uint32_t a;
    asm("{ .reg .u64 t; cvta.to.shared.u64 t, %1; cvt.u32.u64 %0, t; }" : "=r"(a) : "l"(p));
    return a;
}
__device__ __forceinline__ void cp16(uint32_t sa, const void* g) {
    asm volatile("cp.async.cg.shared.global [%0], [%1], 16;" :: "r"(sa), "l"(g));
}
__device__ __forceinline__ void cp_commit() { asm volatile("cp.async.commit_group;" ::: "memory"); }
__device__ __forceinline__ void cp_wait0()  { asm volatile("cp.async.wait_group 0;" ::: "memory"); }
__device__ __forceinline__ void cp_wait1()  { asm volatile("cp.async.wait_group 1;" ::: "memory"); }
__device__ __forceinline__ void cp_wait2()  { asm volatile("cp.async.wait_group 2;" ::: "memory"); }

__device__ __forceinline__ void ldm_x4(uint32_t& r0, uint32_t& r1, uint32_t& r2, uint32_t& r3,
                                       uint32_t a) {
    asm volatile("ldmatrix.sync.aligned.m8n8.x4.shared.b16 {%0,%1,%2,%3}, [%4];"
                 : "=r"(r0), "=r"(r1), "=r"(r2), "=r"(r3) : "r"(a));
}
__device__ __forceinline__ void mma16816(float* d, const uint32_t* a, const uint32_t* b) {
    asm volatile(
        "mma.sync.aligned.m16n8k16.row.col.f32.bf16.bf16.f32 "
        "{%0,%1,%2,%3}, {%4,%5,%6,%7}, {%8,%9}, {%0,%1,%2,%3};"
        : "+f"(d[0]), "+f"(d[1]), "+f"(d[2]), "+f"(d[3])
        : "r"(a[0]), "r"(a[1]), "r"(a[2]), "r"(a[3]), "r"(b[0]), "r"(b[1]));
}
__device__ __forceinline__ void mma16816h(float* d, const uint32_t* a, const uint32_t* b) {
    asm volatile(
        "mma.sync.aligned.m16n8k16.row.col.f32.f16.f16.f32 "
        "{%0,%1,%2,%3}, {%4,%5,%6,%7}, {%8,%9}, {%0,%1,%2,%3};"
        : "+f"(d[0]), "+f"(d[1]), "+f"(d[2]), "+f"(d[3])
        : "r"(a[0]), "r"(a[1]), "r"(a[2]), "r"(a[3]), "r"(b[0]), "r"(b[1]));
}

__device__ __forceinline__ void split2(float v, bf16& h, bf16& l) {
    h = __float2bfloat16(v);
    l = __float2bfloat16(v - __bfloat162float(h));
}
__device__ __forceinline__ void split2h(float v, __half& h, __half& l) {
    h = __float2half_rn(v);
    l = __float2half_rn(v - __half2float(h));
}

// ---------------- conversion kernels ----------------
__global__ void split_kernel(const float* __restrict__ src,
                             bf16* __restrict__ hi, bf16* __restrict__ lo, int n4)
{
    int i = blockIdx.x * 256 + threadIdx.x;
    if (i >= n4) return;
    float4 v = reinterpret_cast<const float4*>(src)[i];
    bf16 h0, l0, h1, l1, h2, l2, h3, l3;
    split2(v.x, h0, l0); split2(v.y, h1, l1); split2(v.z, h2, l2); split2(v.w, h3, l3);
    __nv_bfloat162* H = reinterpret_cast<__nv_bfloat162*>(hi) + 2 * i;
    __nv_bfloat162* L = reinterpret_cast<__nv_bfloat162*>(lo) + 2 * i;
    H[0] = __nv_bfloat162(h0, h1); H[1] = __nv_bfloat162(h2, h3);
    L[0] = __nv_bfloat162(l0, l1); L[1] = __nv_bfloat162(l2, l3);
}

__global__ void cvt16_kernel(const float* __restrict__ src, __half* __restrict__ dst, int n4)
{
    int i = blockIdx.x * 256 + threadIdx.x;
    if (i >= n4) return;
    float4 v = reinterpret_cast<const float4*>(src)[i];
    __half2* D = reinterpret_cast<__half2*>(dst) + 2 * i;
    D[0] = __half2(__float2half_rn(v.x), __float2half_rn(v.y));
    D[1] = __half2(__float2half_rn(v.z), __float2half_rn(v.w));
}

__global__ void embed_kernel(const int* __restrict__ ids,
                             const float* __restrict__ ew,
                             const float* __restrict__ pe,
                             float* __restrict__ x,
                             __half* __restrict__ xh, __half* __restrict__ xl)
{
    int i = blockIdx.x * 256 + threadIdx.x;
    if (i >= SS * DD) return;
    int s = i / DD, d = i - s * DD;
    float v = ew[ids[s] * DD + d] * 27.712812921102035f + pe[i];
    x[i] = v;
    __half h, l; split2h(v, h, l);
    xh[i] = h; xl[i] = l;
}

// ---------------- fp16 2-pass GEMM (hidden layers) — proven skeleton ----------------
#define HSTG 24576
#define H2_SMEM (3 * HSTG + 128)

__global__ __launch_bounds__(256, 2)
void gemm_h2(const __half* __restrict__ Ah, const __half* __restrict__ Al,
             const __half* __restrict__ B, const float* __restrict__ bias,
             float* __restrict__ Cf, __half* __restrict__ C16h, __half* __restrict__ C16l,
             int M, int N, int K, int act)
{
    extern __shared__ char dsm[];
    uint32_t sbase = (smem_u32(dsm) + 127u) & ~127u;

    const int tid = threadIdx.x, lane = tid & 31, wid = tid >> 5;
    const int m0 = blockIdx.x * 128, n0 = blockIdx.y * 128;
    const int warp_m = (wid >> 1) * 32, warp_n = (wid & 1) * 64;

    const __half* gbase[6];
    uint32_t      sofs[6];
#pragma unroll
    for (int t = 0; t < 6; t++) {
        int id = tid + (t << 8);
        int tl = id >> 9;                 // 0:Ah 1:Al 2:B
        int idx = id & 511;
        int r = idx >> 2, j = idx & 3;
        const __half* g;
        if      (tl == 0) g = Ah + (size_t)(m0 + r) * K;
        else if (tl == 1) g = Al + (size_t)(m0 + r) * K;
        else              g = B  + (size_t)(n0 + r) * K;
        gbase[t] = g + j * 8;
        sofs[t]  = (uint32_t)(tl * 8192 + r * 64 + ((j ^ ((r >> 1) & 3)) << 4));
    }

    const int lr = lane & 7, lb1 = (lane >> 3) & 1, lb2 = lane >> 4;
    uint32_t aoff[2][2], boff[4][2];
#pragma unroll
    for (int mi = 0; mi < 2; mi++)
#pragma unroll
        for (int ks = 0; ks < 2; ks++) {
            int r = warp_m + mi * 16 + lr + lb1 * 8;
            int j = ks * 2 + lb2;
            aoff[mi][ks] = (uint32_t)(r * 64 + ((j ^ ((r >> 1) & 3)) << 4));
        }
#pragma unroll
    for (int nb = 0; nb < 4; nb++)
#pragma unroll
        for (int ks = 0; ks < 2; ks++) {
            int r = warp_n + nb * 16 + lr + lb2 * 8;
            int j = ks * 2 + lb1;
            boff[nb][ks] = (uint32_t)(r * 64 + 16384 + ((j ^ ((r >> 1) & 3)) << 4));
        }

    float acc[2][8][4];
#pragma unroll
    for (int mi = 0; mi < 2; mi++)
#pragma unroll
        for (int ni = 0; ni < 8; ni++)
#pragma unroll
            for (int r = 0; r < 4; r++) acc[mi][ni][r] = 0.f;

    const int NC = K >> 5;

    {
        uint32_t st = sbase;
#pragma unroll
        for (int t = 0; t < 6; t++) cp16(st + sofs[t], gbase[t]);
        cp_commit();
        if (NC > 1) {
            st = sbase + HSTG;
#pragma unroll
            for (int t = 0; t < 6; t++) cp16(st + sofs[t], gbase[t] + 32);
            cp_commit();
        }
    }

    int stage = 0;
    for (int c = 0; c < NC; c++) {
        if (c + 2 < NC) {
            int ls = stage + 2; if (ls >= 3) ls -= 3;
            uint32_t st = sbase + ls * HSTG;
            const int koff = (c + 2) << 5;
#pragma unroll
            for (int t = 0; t < 6; t++) cp16(st + sofs[t], gbase[t] + koff);
            cp_commit();
            cp_wait2();
        } else if (c + 1 < NC) {
            cp_wait1();
        } else {
            cp_wait0();
        }
        __syncthreads();

        uint32_t st = sbase + stage * HSTG;
#pragma unroll
        for (int ks = 0; ks < 2; ks++) {
            uint32_t afh[2][4], afl[2][4];
            ldm_x4(afh[0][0], afh[0][1], afh[0][2], afh[0][3], st + aoff[0][ks]);
            ldm_x4(afh[1][0], afh[1][1], afh[1][2], afh[1][3], st + aoff[1][ks]);
            ldm_x4(afl[0][0], afl[0][1], afl[0][2], afl[0][3], st + 8192 + aoff[0][ks]);
            ldm_x4(afl[1][0], afl[1][1], afl[1][2], afl[1][3], st + 8192 + aoff[1][ks]);
#pragma unroll
            for (int nh = 0; nh < 2; nh++) {
                uint32_t bfr[4][2];
                ldm_x4(bfr[0][0], bfr[0][1], bfr[1][0], bfr[1][1], st + boff[2 * nh][ks]);
                ldm_x4(bfr[2][0], bfr[2][1], bfr[3][0], bfr[3][1], st + boff[2 * nh + 1][ks]);
#pragma unroll
                for (int mi = 0; mi < 2; mi++)
#pragma unroll
                    for (int nj = 0; nj < 4; nj++) {
                        mma16816h(acc[mi][4 * nh + nj], afh[mi], bfr[nj]);
                        mma16816h(acc[mi][4 * nh + nj], afl[mi], bfr[nj]);
                    }
            }
        }
        __syncthreads();
        stage++; if (stage >= 3) stage = 0;
    }

#pragma unroll
    for (int mi = 0; mi < 2; mi++) {
        int rbase = m0 + warp_m + mi * 16 + (lane >> 2);
#pragma unroll
        for (int ni = 0; ni < 8; ni++) {
            int col = n0 + warp_n + ni * 8 + (lane & 3) * 2;
            float bv0 = 0.f, bv1 = 0.f;
            if (bias) { bv0 = bias[col]; bv1 = bias[col + 1]; }
#pragma unroll
            for (int hf = 0; hf < 2; hf++) {
                int row = rbase + hf * 8;
                float v0 = acc[mi][ni][hf * 2 + 0] + bv0;
                float v1 = acc[mi][ni][hf * 2 + 1] + bv1;
                if (act) {
                    v0 = 0.5f * v0 * (1.f + erff(v0 * 0.70710678118654752f));
                    v1 = 0.5f * v1 * (1.f + erff(v1 * 0.70710678118654752f));
                }
                size_t idx = (size_t)row * N + col;
                if (Cf) { Cf[idx] = v0; Cf[idx + 1] = v1; }
                if (C16h) {
                    __half h0, l0, h1, l1;
                    split2h(v0, h0, l0); split2h(v1, h1, l1);
                    *reinterpret_cast<__half2*>(C16h + idx) = __half2(h0, h1);
                    *reinterpret_cast<__half2*>(C16l + idx) = __half2(l0, l1);
                }
            }
        }
    }
}

// ---------------- bf16x3 HMMA GEMM (out-proj only) ----------------
#define STG 32768
#define GEMM_SMEM (3 * STG + 128)

__global__ __launch_bounds__(256, 2)
void gemm_mma(const bf16* __restrict__ Ah, const bf16* __restrict__ Al,
              const bf16* __restrict__ Bh, const bf16* __restrict__ Bl,
              const float* __restrict__ bias, float* __restrict__ Cf,
              int M, int N, int K)
{
    extern __shared__ char dsm[];
    uint32_t sbase = (smem_u32(dsm) + 127u) & ~127u;

    const int tid = threadIdx.x, lane = tid & 31, wid = tid >> 5;
    const int m0 = blockIdx.x * 128, n0 = blockIdx.y * 128;
    const int warp_m = (wid >> 1) * 32, warp_n = (wid & 1) * 64;

    const bf16* gbase[8];
    uint32_t    sofs[8];
#pragma unroll
    for (int t = 0; t < 8; t++) {
        int id = tid + (t << 8);
        int tl = id >> 9;
        int idx = id & 511;
        int r = idx >> 2, j = idx & 3;
        const bf16* g;
        if      (tl == 0) g = Ah + (size_t)(m0 + r) * K;
        else if (tl == 1) g = Al + (size_t)(m0 + r) * K;
        else if (tl == 2) g = Bh + (size_t)(n0 + r) * K;
        else              g = Bl + (size_t)(n0 + r) * K;
        gbase[t] = g + j * 8;
        sofs[t]  = (uint32_t)(tl * 8192 + r * 64 + ((j ^ ((r >> 1) & 3)) << 4));
    }

    const int lr = lane & 7, lb1 = (lane >> 3) & 1, lb2 = lane >> 4;
    uint32_t aoff[2][2], boff[4][2];
#pragma unroll
    for (int mi = 0; mi < 2; mi++)
#pragma unroll
        for (int ks = 0; ks < 2; ks++) {
            int r = warp_m + mi * 16 + lr + lb1 * 8;
            int j = ks * 2 + lb2;
            aoff[mi][ks] = (uint32_t)(r * 64 + ((j ^ ((r >> 1) & 3)) << 4));
        }
#pragma unroll
    for (int nb = 0; nb < 4; nb++)
#pragma unroll
        for (int ks = 0; ks < 2; ks++) {
            int r = warp_n + nb * 16 + lr + lb2 * 8;
            int j = ks * 2 + lb1;
            boff[nb][ks] = (uint32_t)(r * 64 + ((j ^ ((r >> 1) & 3)) << 4));
        }

    float acc[2][8][4];
#pragma unroll
    for (int mi = 0; mi < 2; mi++)
#pragma unroll
        for (int ni = 0; ni < 8; ni++)
#pragma unroll
            for (int r = 0; r < 4; r++) acc[mi][ni][r] = 0.f;

    const int NC = K >> 5;

    {
        uint32_t st = sbase;
#pragma unroll
        for (int t = 0; t < 8; t++) cp16(st + sofs[t], gbase[t]);
        cp_commit();
        if (NC > 1) {
            st = sbase + STG;
#pragma unroll
            for (int t = 0; t < 8; t++) cp16(st + sofs[t], gbase[t] + 32);
            cp_commit();
        }
    }

    int stage = 0;
    for (int c = 0; c < NC; c++) {
        if (c + 2 < NC) {
            int ls = stage + 2; if (ls >= 3) ls -= 3;
            uint32_t st = sbase + ls * STG;
            const int koff = (c + 2) << 5;
#pragma unroll
            for (int t = 0; t < 8; t++) cp16(st + sofs[t], gbase[t] + koff);
            cp_commit();
            cp_wait2();
        } else if (c + 1 < NC) {
            cp_wait1();
        } else {
            cp_wait0();
        }
        __syncthreads();

        uint32_t st = sbase + stage * STG;
        const uint32_t ah_b = st, al_b = st + 8192, bh_b = st + 16384, bl_b = st + 24576;
#pragma unroll
        for (int ks = 0; ks < 2; ks++) {
            uint32_t afh[2][4], afl[2][4];
            ldm_x4(afh[0][0], afh[0][1], afh[0][2], afh[0][3], ah_b + aoff[0][ks]);
            ldm_x4(afh[1][0], afh[1][1], afh[1][2], afh[1][3], ah_b + aoff[1][ks]);
            ldm_x4(afl[0][0], afl[0][1], afl[0][2], afl[0][3], al_b + aoff[0][ks]);
            ldm_x4(afl[1][0], afl[1][1], afl[1][2], afl[1][3], al_b + aoff[1][ks]);
#pragma unroll
            for (int nh = 0; nh < 2; nh++) {
                uint32_t bh[4][2], bl[4][2];
                ldm_x4(bh[0][0], bh[0][1], bh[1][0], bh[1][1], bh_b + boff[2 * nh][ks]);
                ldm_x4(bh[2][0], bh[2][1], bh[3][0], bh[3][1], bh_b + boff[2 * nh + 1][ks]);
                ldm_x4(bl[0][0], bl[0][1], bl[1][0], bl[1][1], bl_b + boff[2 * nh][ks]);
                ldm_x4(bl[2][0], bl[2][1], bl[3][0], bl[3][1], bl_b + boff[2 * nh + 1][ks]);
#pragma unroll
                for (int mi = 0; mi < 2; mi++)
#pragma unroll
                    for (int nj = 0; nj < 4; nj++) {
                        mma16816(acc[mi][4 * nh + nj], afh[mi], bh[nj]);
                        mma16816(acc[mi][4 * nh + nj], afh[mi], bl[nj]);
                        mma16816(acc[mi][4 * nh + nj], afl[mi], bh[nj]);
                    }
            }
        }
        __syncthreads();
        stage++; if (stage >= 3) stage = 0;
    }

#pragma unroll
    for (int mi = 0; mi < 2; mi++) {
        int rbase = m0 + warp_m + mi * 16 + (lane >> 2);
#pragma unroll
        for (int ni = 0; ni < 8; ni++) {
            int col = n0 + warp_n + ni * 8 + (lane & 3) * 2;
            float bv0 = bias ? bias[col] : 0.f;
            float bv1 = bias ? bias[col + 1] : 0.f;
#pragma unroll
            for (int hf = 0; hf < 2; hf++) {
                int row = rbase + hf * 8;
                size_t idx = (size_t)row * N + col;
                Cf[idx]     = acc[mi][ni][hf * 2 + 0] + bv0;
                Cf[idx + 1] = acc[mi][ni][hf * 2 + 1] + bv1;
            }
        }
    }
}

// ---------------- LM head GEMM: C = A @ B^T, single-pass fp16 (proven) ----------------
#define LSTG 16384
#define LM_SMEM (4 * LSTG + 128)

__global__ __launch_bounds__(256, 2)
void lm_gemm(const __half* __restrict__ A, const __half* __restrict__ B,
             float* __restrict__ Cf, int M, int N, int K)
{
    extern __shared__ char dsm[];
    uint32_t sbase = (smem_u32(dsm) + 127u) & ~127u;

    const int tid = threadIdx.x, lane = tid & 31, wid = tid >> 5;
    const int m0 = blockIdx.x * 128, n0 = blockIdx.y * 128;
    const int warp_m = (wid >> 1) * 32, warp_n = (wid & 1) * 64;

    const __half* gbase[4];
    uint32_t      sofs[4];
#pragma unroll
    for (int t = 0; t < 4; t++) {
        int id = tid + (t << 8);
        int tl = id >> 9;
        int idx = id & 511;
        int r = idx >> 2, j = idx & 3;
        const __half* g = tl ? (B + (size_t)(n0 + r) * K) : (A + (size_t)(m0 + r) * K);
        gbase[t] = g + j * 8;
        sofs[t]  = (uint32_t)(tl * 8192 + r * 64 + ((j ^ ((r >> 1) & 3)) << 4));
    }

    const int lr = lane & 7, lb1 = (lane >> 3) & 1, lb2 = lane >> 4;
    uint32_t aoff[2][2], boff[4][2];
#pragma unroll
    for (int mi = 0; mi < 2; mi++)
#pragma unroll
        for (int ks = 0; ks < 2; ks++) {
            int r = warp_m + mi * 16 + lr + lb1 * 8;
            int j = ks * 2 + lb2;
            aoff[mi][ks] = (uint32_t)(r * 64 + ((j ^ ((r >> 1) & 3)) << 4));
        }
#pragma unroll
    for (int nb = 0; nb < 4; nb++)
#pragma unroll
        for (int ks = 0; ks < 2; ks++) {
            int r = warp_n + nb * 16 + lr + lb2 * 8;
            int j = ks * 2 + lb1;
            boff[nb][ks] = (uint32_t)(r * 64 + 8192 + ((j ^ ((r >> 1) & 3)) << 4));
        }

    float acc[2][8][4];
#pragma unroll
    for (int mi = 0; mi < 2; mi++)
#pragma unroll
        for (int ni = 0; ni < 8; ni++)
#pragma unroll
            for (int r = 0; r < 4; r++) acc[mi][ni][r] = 0.f;

    const int NC = K >> 5;

    {
        uint32_t st = sbase;
#pragma unroll
        for (int t = 0; t < 4; t++) cp16(st + sofs[t], gbase[t]);
        cp_commit();
        st = sbase + LSTG;
#pragma unroll
        for (int t = 0; t < 4; t++) cp16(st + sofs[t], gbase[t] + 32);
        cp_commit();
    }

    for (int c = 0; c < NC; c++) {
        if (c + 2 < NC) {
            uint32_t st = sbase + ((c + 2) & 3) * LSTG;
            const int koff = (c + 2) << 5;
#pragma unroll
            for (int t = 0; t < 4; t++) cp16(st + sofs[t], gbase[t] + koff);
            cp_commit();
            cp_wait2();
        } else if (c + 1 < NC) {
            cp_wait1();
        } else {
            cp_wait0();
        }
        __syncthreads();

        uint32_t st = sbase + (c & 3) * LSTG;
#pragma unroll
        for (int ks = 0; ks < 2; ks++) {
            uint32_t af[2][4];
            ldm_x4(af[0][0], af[0][1], af[0][2], af[0][3], st + aoff[0][ks]);
            ldm_x4(af[1][0], af[1][1], af[1][2], af[1][3], st + aoff[1][ks]);
#pragma unroll
            for (int nh = 0; nh < 2; nh++) {
                uint32_t bh[4][2];
                ldm_x4(bh[0][0], bh[0][1], bh[1][0], bh[1][1], st + boff[2 * nh][ks]);
                ldm_x4(bh[2][0], bh[2][1], bh[3][0], bh[3][1], st + boff[2 * nh + 1][ks]);
#pragma unroll
                for (int mi = 0; mi < 2; mi++)
#pragma unroll
                    for (int nj = 0; nj < 4; nj++)
                        mma16816h(acc[mi][4 * nh + nj], af[mi], bh[nj]);
            }
        }
    }

#pragma unroll
    for (int mi = 0; mi < 2; mi++) {
        int rbase = m0 + warp_m + mi * 16 + (lane >> 2);
#pragma unroll
        for (int ni = 0; ni < 8; ni++) {
            int col = n0 + warp_n + ni * 8 + (lane & 3) * 2;
#pragma unroll
            for (int hf = 0; hf < 2; hf++) {
                int row = rbase + hf * 8;
                size_t idx = (size_t)row * N + col;
                Cf[idx]     = acc[mi][ni][hf * 2 + 0];
                Cf[idx + 1] = acc[mi][ni][hf * 2 + 1];
            }
        }
    }
}

// ---------------- split-KV flash attention, pass 1 (partials) ----------------
// grid (72, HH): 72 = sum over qb of ceil((2qb+2)/4). Each CTA: one (q-block,
// head, split of <=4 KV tiles). 128 threads, one q row each. fp32 math.
__global__ __launch_bounds__(128)
void attn_split_kernel(const float* __restrict__ qkv,
                       float* __restrict__ mpart, float* __restrict__ lpart,
                       float* __restrict__ accpart)
{
    __shared__ float Ks[64][64];
    __shared__ float Vs[64][64];

    const int h = blockIdx.y;
    const int tid = threadIdx.x;

    // map blockIdx.x -> (qb, sp)
    int rem = blockIdx.x, qb = 0;
    for (; qb < 16; qb++) {
        int ns = (2 * qb + 5) >> 2;
        if (rem < ns) break;
        rem -= ns;
    }
    const int sp = rem;
    const int ntiles = 2 * qb + 2;
    const int t0 = sp * 4;
    const int t1 = (t0 + 4 < ntiles) ? t0 + 4 : ntiles;

    const int q_idx = qb * 128 + tid;

    float q[HDIM];
    const float* qrow = qkv + (size_t)q_idx * (3 * DD) + h * HDIM;
#pragma unroll
    for (int d = 0; d < HDIM; d++) q[d] = qrow[d];

    float m = -1e30f, l = 0.f;
    float acc[HDIM];
#pragma unroll
    for (int d = 0; d < HDIM; d++) acc[d] = 0.f;

    for (int kt = t0; kt < t1; kt++) {
#pragma unroll
        for (int r = 0; r < 8; r++) {
            int id  = tid + r * 128;
            int row = id >> 4;
            int c4  = (id & 15) << 2;
            const float* base = qkv + (size_t)(kt * 64 + row) * (3 * DD) + h * HDIM + c4;
            *reinterpret_cast<float4*>(&Ks[row][c4]) = *reinterpret_cast<const float4*>(base + DD);
            *reinterpret_cast<float4*>(&Vs[row][c4]) = *reinterpret_cast<const float4*>(base + 2 * DD);
        }
        __syncthreads();

#pragma unroll
        for (int sub = 0; sub < 2; sub++) {
            const int base = kt * 64 + sub * 32;
            if (base <= q_idx) {
                int jmax = q_idx - base;
                if (jmax > 31) jmax = 31;

                float s[32];
                float smax = -1e30f;
                for (int j = 0; j <= jmax; j++) {
                    float acc_s = 0.f;
#pragma unroll
                    for (int d = 0; d < HDIM; d++) acc_s += q[d] * Ks[sub * 32 + j][d];
                    acc_s *= 0.125f;
                    s[j] = acc_s;
                    smax = fmaxf(smax, acc_s);
                }
                float mnew = fmaxf(m, smax);
                float corr = __expf(m - mnew);
                l *= corr;
#pragma unroll
                for (int d = 0; d < HDIM; d++) acc[d] *= corr;
                for (int j = 0; j <= jmax; j++) {
                    float p = __expf(s[j] - mnew);
                    l += p;
#pragma unroll
                    for (int d = 0; d < HDIM; d++) acc[d] += p * Vs[sub * 32 + j][d];
                }
                m = mnew;
            }
        }
        __syncthreads();
    }

    // write partial (SoA, q-major -> coalesced)
    const int slot = (h * MAXSP + sp) * SS + q_idx;
    mpart[slot] = m;
    lpart[slot] = l;
#pragma unroll
    for (int d = 0; d < HDIM; d++)
        accpart[((size_t)((h * MAXSP + sp) * HDIM + d)) * SS + q_idx] = acc[d];
}

// ---------------- split-KV flash attention, pass 2 (combine) ----------------
// One thread per (head, q row); idx = h*SS + q so consecutive threads share h,
// consecutive q -> coalesced partial reads.
__global__ __launch_bounds__(256)
void attn_combine_kernel(const float* __restrict__ mpart, const float* __restrict__ lpart,
                         const float* __restrict__ accpart,
                         bf16* __restrict__ oh, bf16* __restrict__ ol)
{
    int idx = blockIdx.x * 256 + threadIdx.x;
    if (idx >= HH * SS) return;
    const int h = idx / SS;
    const int q = idx - h * SS;
    const int qb = q >> 7;
    const int ns = (2 * qb + 5) >> 2;

    float M = -1e30f;
    float ms[MAXSP];
    for (int s = 0; s < ns; s++) {
        ms[s] = mpart[(h * MAXSP + s) * SS + q];
        M = fmaxf(M, ms[s]);
    }
    float w[MAXSP];
    float L = 0.f;
    for (int s = 0; s < ns; s++) {
        w[s] = __expf(ms[s] - M);
        L += lpart[(h * MAXSP + s) * SS + q] * w[s];
    }
    float inv = 1.f / L;

    size_t ob = (size_t)q * DD + h * HDIM;
#pragma unroll
    for (int d = 0; d < HDIM; d++) {
        float v = 0.f;
        for (int s = 0; s < ns; s++)
            v += accpart[((size_t)((h * MAXSP + s) * HDIM + d)) * SS + q] * w[s];
        v *= inv;
        bf16 hh, ll; split2(v, hh, ll);
        oh[ob + d] = hh; ol[ob + d] = ll;
    }
}

// ---------------- add + LayerNorm (fp32 out and/or fp16 hi/lo out) ----------------
__device__ __forceinline__ float warp_sum(float v)
{
#pragma unroll
    for (int o = 16; o > 0; o >>= 1) v += __shfl_xor_sync(0xffffffffu, v, o);
    return v;
}

__global__ __launch_bounds__(256)
void add_ln_kernel(const float* __restrict__ x, const float* __restrict__ y,
                   const float* __restrict__ g, const float* __restrict__ b,
                   float* __restrict__ out,
                   __half* __restrict__ outh, __half* __restrict__ outl)
{
    __shared__ float buf[DD];
    __shared__ float red[8];
    const int row = blockIdx.x;
    const int tid = threadIdx.x;
    const int wid = tid >> 5, lane = tid & 31;

    float local = 0.f;
    for (int d = tid; d < DD; d += 256) {
        float v = x[(size_t)row * DD + d] + y[(size_t)row * DD + d];
        buf[d] = v;
        local += v;
    }
    local = warp_sum(local);
    if (lane == 0) red[wid] = local;
    __syncthreads();
    float tot = (lane < 8) ? red[lane] : 0.f;
    tot = warp_sum(tot);
    float mu = __shfl_sync(0xffffffffu, tot, 0) * (1.f / DD);

    float lv = 0.f;
    for (int d = tid; d < DD; d += 256) {
        float t = buf[d] - mu;
        lv += t * t;
    }
    lv = warp_sum(lv);
    __syncthreads();
    if (lane == 0) red[wid] = lv;
    __syncthreads();
    float tv = (lane < 8) ? red[lane] : 0.f;
    tv = warp_sum(tv);
    float rstd = rsqrtf(__shfl_sync(0xffffffffu, tv, 0) * (1.f / DD) + EPS);

    for (int d = tid; d < DD; d += 256) {
        float v = (buf[d] - mu) * rstd * g[d] + b[d];
        size_t idx = (size_t)row * DD + d;
        if (out) out[idx] = v;
        if (outh) {
            if (outl) {
                __half h, l; split2h(v, h, l);
                outh[idx] = h; outl[idx] = l;
            } else {
                outh[idx] = __float2half_rn(v);
            }
        }
    }
}

// ---------------- launch ----------------
extern "C" void kernel_launch(void* const* d_in, const int* in_sizes, int n_in,
                              void* d_out, int out_size)
{
    const int*   ids = (const int*)  d_in[0];
    const float* ew  = (const float*)d_in[1];
    const float* pe  = (const float*)d_in[2];
    const float* inw = (const float*)d_in[3];
    const float* inb = (const float*)d_in[4];
    const float* ow  = (const float*)d_in[5];
    const float* ob  = (const float*)d_in[6];
    const float* ng  = (const float*)d_in[7];
    const float* nb  = (const float*)d_in[8];
    const float* w1  = (const float*)d_in[9];
    const float* b1  = (const float*)d_in[10];
    const float* w2  = (const float*)d_in[11];
    const float* b2  = (const float*)d_in[12];
    const float* lmw = (const float*)d_in[13];
    float* out = (float*)d_out;

    float *x, *qkv, *proj, *ln1, *f2, *mp, *lp, *ap;
    bf16 *oh, *ol, *woh, *wol;
    __half *xh16, *xl16, *l1h16, *l1l16, *f1h16, *f1l16, *x16;
    __half *wi16, *w116, *w216, *lm16;
    cudaGetSymbolAddress((void**)&x,    g_x);
    cudaGetSymbolAddress((void**)&qkv,  g_qkv);
    cudaGetSymbolAddress((void**)&proj, g_proj);
    cudaGetSymbolAddress((void**)&ln1,  g_ln1);
    cudaGetSymbolAddress((void**)&f2,   g_f2);
    cudaGetSymbolAddress((void**)&mp,   g_mpart);
    cudaGetSymbolAddress((void**)&lp,   g_lpart);
    cudaGetSymbolAddress((void**)&ap,   g_accpart);
    cudaGetSymbolAddress((void**)&oh,   g_oh);  cudaGetSymbolAddress((void**)&ol,  g_ol);
    cudaGetSymbolAddress((void**)&woh,  g_woh); cudaGetSymbolAddress((void**)&wol, g_wol);
    cudaGetSymbolAddress((void**)&xh16, g_xh16);  cudaGetSymbolAddress((void**)&xl16, g_xl16);
    cudaGetSymbolAddress((void**)&l1h16,g_l1h16); cudaGetSymbolAddress((void**)&l1l16,g_l1l16);
    cudaGetSymbolAddress((void**)&f1h16,g_f1h16); cudaGetSymbolAddress((void**)&f1l16,g_f1l16);
    cudaGetSymbolAddress((void**)&x16,  g_x16);
    cudaGetSymbolAddress((void**)&wi16, g_wi16);
    cudaGetSymbolAddress((void**)&w116, g_w116);
    cudaGetSymbolAddress((void**)&w216, g_w216);
    cudaGetSymbolAddress((void**)&lm16, g_lm16);

    cudaFuncSetAttribute(gemm_mma, cudaFuncAttributeMaxDynamicSharedMemorySize, GEMM_SMEM);
    cudaFuncSetAttribute(gemm_h2,  cudaFuncAttributeMaxDynamicSharedMemorySize, H2_SMEM);
    cudaFuncSetAttribute(lm_gemm,  cudaFuncAttributeMaxDynamicSharedMemorySize, LM_SMEM);

    // weight conversions
    cvt16_kernel<<<(3 * DD * DD / 4 + 255) / 256, 256>>>(inw, wi16, 3 * DD * DD / 4);
    cvt16_kernel<<<(DFF * DD / 4 + 255) / 256, 256>>>(w1, w116, DFF * DD / 4);
    cvt16_kernel<<<(DD * DFF / 4 + 255) / 256, 256>>>(w2, w216, DD * DFF / 4);
    cvt16_kernel<<<(VV * DD / 4 + 255) / 256, 256>>>(lmw, lm16, VV * DD / 4);

    // embed (+fp16 hi/lo split)
    embed_kernel<<<(SS * DD + 255) / 256, 256>>>(ids, ew, pe, x, xh16, xl16);

    // qkv = x @ in_proj_w^T + b   [2048, 2304]  (fp16 2-pass)
    gemm_h2<<<dim3(SS / 128, (3 * DD) / 128), 256, H2_SMEM>>>(
        xh16, xl16, wi16, inb, qkv, nullptr, nullptr, SS, 3 * DD, DD, 0);

    // out-proj weight split (bf16 hi/lo)
    split_kernel<<<(DD * DD / 4 + 255) / 256, 256>>>(ow, woh, wol, DD * DD / 4);

    // attention: split-KV partials, then combine -> o (bf16 hi/lo)
    attn_split_kernel<<<dim3(72, HH), 128>>>(qkv, mp, lp, ap);
    attn_combine_kernel<<<(HH * SS + 255) / 256, 256>>>(mp, lp, ap, oh, ol);

    // out proj (bf16x3)           [2048, 768]
    gemm_mma<<<dim3(SS / 128, DD / 128), 256, GEMM_SMEM>>>(
        oh, ol, woh, wol, ob, proj, SS, DD, DD);

    // ln1 = LN(x + proj) -> fp32 + fp16 hi/lo
    add_ln_kernel<<<SS, 256>>>(x, proj, ng, nb, ln1, l1h16, l1l16);

    // f1 = gelu(ln1 @ w1^T + b1) [2048, 3072] -> fp16 hi/lo (fp16 2-pass)
    gemm_h2<<<dim3(SS / 128, DFF / 128), 256, H2_SMEM>>>(
        l1h16, l1l16, w116, b1, nullptr, f1h16, f1l16, SS, DFF, DD, 1);

    // f2 = f1 @ w2^T + b2        [2048, 768] (fp16 2-pass)
    gemm_h2<<<dim3(SS / 128, DD / 128), 256, H2_SMEM>>>(
        f1h16, f1l16, w216, b2, f2, nullptr, nullptr, SS, DD, DFF, 0);

    // x2 = LN(ln1 + f2) -> fp16 single
    add_ln_kernel<<<SS, 256>>>(ln1, f2, ng, nb, nullptr, x16, nullptr);

    // logits = x2 @ lm16^T       [2048, 32000] single-pass fp16
    lm_gemm<<<dim3(SS / 128, VV / 128), 256, LM_SMEM>>>(x16, lm16, out, SS, VV, DD);
}